// round 9
// baseline (speedup 1.0000x reference)
#include <cuda_runtime.h>
#include <cuda_bf16.h>
#include <cstdint>

#define NMAX 100000
#define EMAX 1700000
#define F 128

// ------------------------- device-global scratch ---------------------------
__device__ float g_s1[(size_t)NMAX * F];
__device__ float g_s2[(size_t)NMAX * F];
__device__ float g_x1[(size_t)NMAX * F];
__device__ float g_x2[(size_t)NMAX * F];
__device__ int   g_off1[NMAX], g_cur1[NMAX];
__device__ int   g_off2[NMAX], g_cur2[NMAX];
__device__ int2  g_e1[EMAX], g_e2[EMAX];     // interleaved {src, w-bits}
__device__ int   g_part1[512], g_part2[512];

// ------------------------------- CSR build ---------------------------------
__global__ void hist_dual(const int* __restrict__ d1, int E1, int* __restrict__ c1,
                          const int* __restrict__ d2, int E2, int* __restrict__ c2)
{
    int i = blockIdx.x * blockDim.x + threadIdx.x;
    int stride = gridDim.x * blockDim.x;
    const int q1 = E1 >> 2, q2 = E2 >> 2;
    const int total = q1 + q2;
    for (int j = i; j < total; j += stride) {
        if (j < q1) {
            int4 v = __ldg((const int4*)d1 + j);
            atomicAdd(&c1[v.x], 1); atomicAdd(&c1[v.y], 1);
            atomicAdd(&c1[v.z], 1); atomicAdd(&c1[v.w], 1);
        } else {
            int4 v = __ldg((const int4*)d2 + (j - q1));
            atomicAdd(&c2[v.x], 1); atomicAdd(&c2[v.y], 1);
            atomicAdd(&c2[v.z], 1); atomicAdd(&c2[v.w], 1);
        }
    }
    if (i < (E1 & 3)) atomicAdd(&c1[d1[(q1 << 2) + i]], 1);
    else if (i >= 4 && i - 4 < (E2 & 3)) atomicAdd(&c2[d2[(q2 << 2) + i - 4]], 1);
}

__global__ void __launch_bounds__(512) scanA_kernel(
    const int* __restrict__ cnt1, int* __restrict__ off1, int* __restrict__ p1,
    const int* __restrict__ cnt2, int* __restrict__ off2, int* __restrict__ p2,
    int N)
{
    const int* cnt = blockIdx.y ? cnt2 : cnt1;
    int* off       = blockIdx.y ? off2 : off1;
    int* partial   = blockIdx.y ? p2   : p1;
    __shared__ int sh[512];
    int t = threadIdx.x;
    int i = blockIdx.x * 512 + t;
    int v = (i < N) ? cnt[i] : 0;
    sh[t] = v;
    __syncthreads();
#pragma unroll
    for (int d = 1; d < 512; d <<= 1) {
        int u = (t >= d) ? sh[t - d] : 0;
        __syncthreads();
        sh[t] += u;
        __syncthreads();
    }
    if (i < N) off[i] = sh[t] - v;
    if (t == 511) partial[blockIdx.x] = sh[511];
}

__global__ void __launch_bounds__(512) scanB_kernel(
    int* __restrict__ p1, int* __restrict__ p2, int NB)
{
    int* partial = blockIdx.x ? p2 : p1;
    __shared__ int sh[512];
    int t = threadIdx.x;
    int v = (t < NB) ? partial[t] : 0;
    sh[t] = v;
    __syncthreads();
#pragma unroll
    for (int d = 1; d < 512; d <<= 1) {
        int u = (t >= d) ? sh[t - d] : 0;
        __syncthreads();
        sh[t] += u;
        __syncthreads();
    }
    if (t < NB) partial[t] = sh[t] - v;
}

__global__ void scanC_kernel(int* __restrict__ off1, const int* __restrict__ p1,
                             int* __restrict__ cur1,
                             int* __restrict__ off2, const int* __restrict__ p2,
                             int* __restrict__ cur2, int N)
{
    int* off        = blockIdx.y ? off2 : off1;
    const int* pb   = blockIdx.y ? p2   : p1;
    int* cur        = blockIdx.y ? cur2 : cur1;
    int i = blockIdx.x * blockDim.x + threadIdx.x;
    int stride = gridDim.x * blockDim.x;
    for (; i < N; i += stride) {
        int o = off[i] + pb[i >> 9];
        off[i] = o;
        cur[i] = o;
    }
}

__global__ void fill_dual(
    const int* __restrict__ s1, const int* __restrict__ d1, const float* __restrict__ w1,
    int E1, int* __restrict__ c1, int2* __restrict__ eo1,
    const int* __restrict__ s2, const int* __restrict__ d2, const float* __restrict__ w2,
    int E2, int* __restrict__ c2, int2* __restrict__ eo2)
{
    int i = blockIdx.x * blockDim.x + threadIdx.x;
    int stride = gridDim.x * blockDim.x;
    const int q1 = E1 >> 2, q2 = E2 >> 2;
    const int total = q1 + q2;
    for (int j = i; j < total; j += stride) {
        if (j < q1) {
            int4   dv = __ldg((const int4*)d1 + j);
            int4   sv = __ldg((const int4*)s1 + j);
            float4 wv = __ldg((const float4*)w1 + j);
            int p;
            p = atomicAdd(&c1[dv.x], 1); eo1[p] = make_int2(sv.x, __float_as_int(wv.x));
            p = atomicAdd(&c1[dv.y], 1); eo1[p] = make_int2(sv.y, __float_as_int(wv.y));
            p = atomicAdd(&c1[dv.z], 1); eo1[p] = make_int2(sv.z, __float_as_int(wv.z));
            p = atomicAdd(&c1[dv.w], 1); eo1[p] = make_int2(sv.w, __float_as_int(wv.w));
        } else {
            int k = j - q1;
            int4   dv = __ldg((const int4*)d2 + k);
            int4   sv = __ldg((const int4*)s2 + k);
            float4 wv = __ldg((const float4*)w2 + k);
            int p;
            p = atomicAdd(&c2[dv.x], 1); eo2[p] = make_int2(sv.x, __float_as_int(wv.x));
            p = atomicAdd(&c2[dv.y], 1); eo2[p] = make_int2(sv.y, __float_as_int(wv.y));
            p = atomicAdd(&c2[dv.z], 1); eo2[p] = make_int2(sv.z, __float_as_int(wv.z));
            p = atomicAdd(&c2[dv.w], 1); eo2[p] = make_int2(sv.w, __float_as_int(wv.w));
        }
    }
    if (i < (E1 & 3)) {
        int k = (q1 << 2) + i;
        int p = atomicAdd(&c1[d1[k]], 1);
        eo1[p] = make_int2(s1[k], __float_as_int(w1[k]));
    } else if (i >= 4 && i - 4 < (E2 & 3)) {
        int k = (q2 << 2) + (i - 4);
        int p = atomicAdd(&c2[d2[k]], 1);
        eo2[p] = make_int2(s2[k], __float_as_int(w2[k]));
    }
}

// ------------------------------ mma helpers ---------------------------------
__device__ __forceinline__ void ldsm_x4(uint32_t* r, uint32_t addr) {
    asm volatile("ldmatrix.sync.aligned.m8n8.x4.shared.b16 {%0,%1,%2,%3}, [%4];"
                 : "=r"(r[0]), "=r"(r[1]), "=r"(r[2]), "=r"(r[3]) : "r"(addr));
}
__device__ __forceinline__ void ldsm_x2t(uint32_t& r0, uint32_t& r1, uint32_t addr) {
    asm volatile("ldmatrix.sync.aligned.m8n8.x2.trans.shared.b16 {%0,%1}, [%2];"
                 : "=r"(r0), "=r"(r1) : "r"(addr));
}
__device__ __forceinline__ void mma_bf16(float* d, const uint32_t* a, uint32_t b0, uint32_t b1) {
    asm volatile("mma.sync.aligned.m16n8k16.row.col.f32.bf16.bf16.f32 "
                 "{%0,%1,%2,%3}, {%4,%5,%6,%7}, {%8,%9}, {%0,%1,%2,%3};"
                 : "+f"(d[0]), "+f"(d[1]), "+f"(d[2]), "+f"(d[3])
                 : "r"(a[0]), "r"(a[1]), "r"(a[2]), "r"(a[3]), "r"(b0), "r"(b1));
}

#define A_STRIDE 24

// ------------------- Kernel A: dual gather + interleaved xW0 ----------------
// Every kstride-th block computes a 128-row tile of C = x@W0 + (b0+b1+b2);
// the rest perform the CSR gathers for both graphs (R4-exact inner loop).
__global__ void __launch_bounds__(512, 2) mixed_gather_xw0(
    const float4* __restrict__ x4,
    const int* __restrict__ off1, const int* __restrict__ end1,
    const int2* __restrict__ e1, float4* __restrict__ s1o,
    const int* __restrict__ off2, const int* __restrict__ end2,
    const int2* __restrict__ e2, float4* __restrict__ s2o,
    const float* __restrict__ W0,
    const float* __restrict__ b0, const float* __restrict__ b1, const float* __restrict__ b2,
    float* __restrict__ C, int M, int sgrid, int kstride)
{
    __shared__ union {
        int2 se[16][32];
        struct {
            __nv_bfloat16 Ahi[128 * A_STRIDE];
            __nv_bfloat16 Alo[128 * A_STRIDE];
            __nv_bfloat16 Bhi[16 * 128];
            __nv_bfloat16 Blo[16 * 128];
            float bsum[128];
        } g;
    } sm;

    const int bid  = blockIdx.x;
    const int tid  = threadIdx.x;
    const int lane = tid & 31;
    const int wid  = tid >> 5;

    if (bid % kstride == kstride - 1) {
        // ---------------- xW0 GEMM tile ----------------
        const int row0 = (bid / kstride) * 128;

        if (tid < 128)
            sm.g.bsum[tid] = __ldg(b0 + tid) + __ldg(b1 + tid) + __ldg(b2 + tid);

        float acc[2][4][4];
#pragma unroll
        for (int mt = 0; mt < 2; mt++)
#pragma unroll
            for (int nt = 0; nt < 4; nt++)
#pragma unroll
                for (int q = 0; q < 4; q++) acc[mt][nt][q] = 0.f;

        const int wm = (wid >> 2) * 32;   // 0,32,64,96
        const int wn = (wid & 3) * 32;    // 0,32,64,96

        const uint32_t sAhi = (uint32_t)__cvta_generic_to_shared(sm.g.Ahi);
        const uint32_t sAlo = (uint32_t)__cvta_generic_to_shared(sm.g.Alo);
        const uint32_t sBhi = (uint32_t)__cvta_generic_to_shared(sm.g.Bhi);
        const uint32_t sBlo = (uint32_t)__cvta_generic_to_shared(sm.g.Blo);
        const float* A = (const float*)x4;

#pragma unroll 1
        for (int kk = 0; kk < 8; kk++) {
            const int k0 = kk * 16;
            __syncthreads();
            if (tid < 256) {
                const int alr   = tid >> 1;
                const int akoff = (tid & 1) * 8;
                float f[8] = {0, 0, 0, 0, 0, 0, 0, 0};
                if (row0 + alr < M) {
                    const float* ap = A + (size_t)(row0 + alr) * F + k0 + akoff;
                    float4 fa = *reinterpret_cast<const float4*>(ap);
                    float4 fb = *reinterpret_cast<const float4*>(ap + 4);
                    f[0] = fa.x; f[1] = fa.y; f[2] = fa.z; f[3] = fa.w;
                    f[4] = fb.x; f[5] = fb.y; f[6] = fb.z; f[7] = fb.w;
                }
                union { __nv_bfloat16 b[8]; uint4 u; } H, L;
#pragma unroll
                for (int q = 0; q < 8; q++) {
                    H.b[q] = __float2bfloat16(f[q]);
                    L.b[q] = __float2bfloat16(f[q] - __bfloat162float(H.b[q]));
                }
                *reinterpret_cast<uint4*>(&sm.g.Ahi[alr * A_STRIDE + akoff]) = H.u;
                *reinterpret_cast<uint4*>(&sm.g.Alo[alr * A_STRIDE + akoff]) = L.u;

                const int bk = tid >> 4;      // 0..15
                const int bj = tid & 15;      // 0..15
                const float* bp = W0 + (size_t)(k0 + bk) * F + bj * 8;
                float4 ga = *reinterpret_cast<const float4*>(bp);
                float4 gb = *reinterpret_cast<const float4*>(bp + 4);
                float h[8] = {ga.x, ga.y, ga.z, ga.w, gb.x, gb.y, gb.z, gb.w};
                union { __nv_bfloat16 b[8]; uint4 u; } BH, BL;
#pragma unroll
                for (int q = 0; q < 8; q++) {
                    BH.b[q] = __float2bfloat16(h[q]);
                    BL.b[q] = __float2bfloat16(h[q] - __bfloat162float(BH.b[q]));
                }
                const int cpos = bk * 128 + ((bj ^ (bk & 7)) * 8);
                *reinterpret_cast<uint4*>(&sm.g.Bhi[cpos]) = BH.u;
                *reinterpret_cast<uint4*>(&sm.g.Blo[cpos]) = BL.u;
            }
            __syncthreads();

            uint32_t ahi[2][4], alo[2][4];
#pragma unroll
            for (int mt = 0; mt < 2; mt++) {
                const int rl = wm + mt * 16 + (lane & 15);
                const uint32_t aoff = (uint32_t)(rl * (A_STRIDE * 2)) + ((lane >> 4) << 4);
                ldsm_x4(ahi[mt], sAhi + aoff);
                ldsm_x4(alo[mt], sAlo + aoff);
            }
#pragma unroll
            for (int nt = 0; nt < 4; nt++) {
                const int kl = lane & 15;
                const int chunk = ((wn >> 3) + nt) ^ (kl & 7);
                const uint32_t boff = (uint32_t)(kl * 256) + (uint32_t)(chunk << 4);
                uint32_t bh0, bh1, bl0, bl1;
                ldsm_x2t(bh0, bh1, sBhi + boff);
                ldsm_x2t(bl0, bl1, sBlo + boff);
#pragma unroll
                for (int mt = 0; mt < 2; mt++) {
                    mma_bf16(acc[mt][nt], ahi[mt], bh0, bh1);
                    mma_bf16(acc[mt][nt], ahi[mt], bl0, bl1);
                    mma_bf16(acc[mt][nt], alo[mt], bh0, bh1);
                }
            }
        }
        __syncthreads();

        const int gq = lane >> 2;
        const int tq = lane & 3;
#pragma unroll
        for (int mt = 0; mt < 2; mt++) {
            const int r0 = row0 + wm + mt * 16 + gq;
            const int r1 = r0 + 8;
#pragma unroll
            for (int nt = 0; nt < 4; nt++) {
                const int c0 = wn + nt * 8 + 2 * tq;
                const float bs0 = sm.g.bsum[c0], bs1 = sm.g.bsum[c0 + 1];
                if (r0 < M) {
                    float2 v = make_float2(acc[mt][nt][0] + bs0, acc[mt][nt][1] + bs1);
                    *reinterpret_cast<float2*>(C + (size_t)r0 * F + c0) = v;
                }
                if (r1 < M) {
                    float2 v = make_float2(acc[mt][nt][2] + bs0, acc[mt][nt][3] + bs1);
                    *reinterpret_cast<float2*>(C + (size_t)r1 * F + c0) = v;
                }
            }
        }
    } else {
        // ---------------- dual-graph CSR gather (R4-exact inner loop) -------
        const int g = bid - bid / kstride;
        if (g >= sgrid) return;
        const int gw = g * 16 + wid;
        if (gw >= 2 * M) return;

        const bool g2  = (gw >= M);
        const int row  = g2 ? gw - M : gw;
        const int* off    = g2 ? off2 : off1;
        const int* end    = g2 ? end2 : end1;
        const int2* edges = g2 ? e2 : e1;
        float4* out4      = g2 ? s2o : s1o;

        const int beg = __ldg(off + row);
        const int en  = __ldg(end + row);

        float4 acc = make_float4(0.f, 0.f, 0.f, 0.f);

        for (int j = beg; j < en; j += 32) {
            const int cnt = min(32, en - j);
            int2 e = make_int2(0, 0);                 // w=0 pad -> contributes 0
            if (lane < cnt) e = __ldg(edges + j + lane);
            sm.se[wid][lane] = e;
            __syncwarp();

            const int cnt8 = (cnt + 7) & ~7;
#pragma unroll 1
            for (int t = 0; t < cnt8; t += 8) {
                float4 v[8];
                float  w[8];
#pragma unroll
                for (int u = 0; u < 8; u++) {
                    int2 ee = sm.se[wid][t + u];
                    w[u] = __int_as_float(ee.y);
                    v[u] = __ldg(x4 + (size_t)ee.x * 32 + lane);
                }
#pragma unroll
                for (int u = 0; u < 8; u++) {
                    acc.x += w[u] * v[u].x;
                    acc.y += w[u] * v[u].y;
                    acc.z += w[u] * v[u].z;
                    acc.w += w[u] * v[u].w;
                }
            }
            __syncwarp();
        }
        out4[(size_t)row * 32 + lane] = acc;
    }
}

// -------------- Kernel B: C += s1@W1 + s2@W2 (2-source accum GEMM) ----------
__global__ void __launch_bounds__(256, 2) gemm2_acc(
    const float* __restrict__ A0, const float* __restrict__ A1,
    const float* __restrict__ B0, const float* __restrict__ B1,
    float* __restrict__ C, int M)
{
    __shared__ __nv_bfloat16 Ahi[128 * A_STRIDE];
    __shared__ __nv_bfloat16 Alo[128 * A_STRIDE];
    __shared__ __nv_bfloat16 Bhi[16 * 128];
    __shared__ __nv_bfloat16 Blo[16 * 128];

    const int tid  = threadIdx.x;
    const int lane = tid & 31;
    const int wid  = tid >> 5;
    const int row0 = blockIdx.x * 128;

    const int wm = (wid >> 1) * 32;
    const int wn = (wid & 1) * 64;

    float acc[2][8][4];
#pragma unroll
    for (int mt = 0; mt < 2; mt++)
#pragma unroll
        for (int nt = 0; nt < 8; nt++)
#pragma unroll
            for (int q = 0; q < 4; q++) acc[mt][nt][q] = 0.f;

    const int alr   = tid >> 1;
    const int akoff = (tid & 1) * 8;
    const bool arow_ok = (row0 + alr) < M;
    const int bk = tid >> 4;
    const int bj = tid & 15;

    const uint32_t sAhi = (uint32_t)__cvta_generic_to_shared(Ahi);
    const uint32_t sAlo = (uint32_t)__cvta_generic_to_shared(Alo);
    const uint32_t sBhi = (uint32_t)__cvta_generic_to_shared(Bhi);
    const uint32_t sBlo = (uint32_t)__cvta_generic_to_shared(Blo);

    const float* Alist[2] = {A0, A1};
    const float* Blist[2] = {B0, B1};

    for (int s = 0; s < 2; s++) {
        const float* A = Alist[s];
        const float* B = Blist[s];

#pragma unroll 1
        for (int kk = 0; kk < 8; kk++) {
            const int k0 = kk * 16;
            __syncthreads();

            {
                float f[8] = {0, 0, 0, 0, 0, 0, 0, 0};
                if (arow_ok) {
                    const float* ap = A + (size_t)(row0 + alr) * F + k0 + akoff;
                    float4 fa = *reinterpret_cast<const float4*>(ap);
                    float4 fb = *reinterpret_cast<const float4*>(ap + 4);
                    f[0] = fa.x; f[1] = fa.y; f[2] = fa.z; f[3] = fa.w;
                    f[4] = fb.x; f[5] = fb.y; f[6] = fb.z; f[7] = fb.w;
                }
                union { __nv_bfloat16 b[8]; uint4 u; } H, L;
#pragma unroll
                for (int q = 0; q < 8; q++) {
                    H.b[q] = __float2bfloat16(f[q]);
                    L.b[q] = __float2bfloat16(f[q] - __bfloat162float(H.b[q]));
                }
                *reinterpret_cast<uint4*>(&Ahi[alr * A_STRIDE + akoff]) = H.u;
                *reinterpret_cast<uint4*>(&Alo[alr * A_STRIDE + akoff]) = L.u;
            }
            {
                const float* bp = B + (size_t)(k0 + bk) * F + bj * 8;
                float4 fa = *reinterpret_cast<const float4*>(bp);
                float4 fb = *reinterpret_cast<const float4*>(bp + 4);
                float f[8] = {fa.x, fa.y, fa.z, fa.w, fb.x, fb.y, fb.z, fb.w};
                union { __nv_bfloat16 b[8]; uint4 u; } H, L;
#pragma unroll
                for (int q = 0; q < 8; q++) {
                    H.b[q] = __float2bfloat16(f[q]);
                    L.b[q] = __float2bfloat16(f[q] - __bfloat162float(H.b[q]));
                }
                const int cpos = bk * 128 + ((bj ^ (bk & 7)) * 8);
                *reinterpret_cast<uint4*>(&Bhi[cpos]) = H.u;
                *reinterpret_cast<uint4*>(&Blo[cpos]) = L.u;
            }
            __syncthreads();

            uint32_t ahi[2][4], alo[2][4];
#pragma unroll
            for (int mt = 0; mt < 2; mt++) {
                const int rl = wm + mt * 16 + (lane & 15);
                const uint32_t aoff = (uint32_t)(rl * (A_STRIDE * 2)) + ((lane >> 4) << 4);
                ldsm_x4(ahi[mt], sAhi + aoff);
                ldsm_x4(alo[mt], sAlo + aoff);
            }
#pragma unroll
            for (int nt = 0; nt < 8; nt++) {
                const int kl = lane & 15;
                const int chunk = ((wn >> 3) + nt) ^ (kl & 7);
                const uint32_t boff = (uint32_t)(kl * 256) + (uint32_t)(chunk << 4);
                uint32_t bh0, bh1, bl0, bl1;
                ldsm_x2t(bh0, bh1, sBhi + boff);
                ldsm_x2t(bl0, bl1, sBlo + boff);
#pragma unroll
                for (int mt = 0; mt < 2; mt++) {
                    mma_bf16(acc[mt][nt], ahi[mt], bh0, bh1);
                    mma_bf16(acc[mt][nt], ahi[mt], bl0, bl1);
                    mma_bf16(acc[mt][nt], alo[mt], bh0, bh1);
                }
            }
        }
    }

    const int g = lane >> 2;
    const int t = lane & 3;
#pragma unroll
    for (int mt = 0; mt < 2; mt++) {
        const int r0 = row0 + wm + mt * 16 + g;
        const int r1 = r0 + 8;
#pragma unroll
        for (int nt = 0; nt < 8; nt++) {
            const int c0 = wn + nt * 8 + 2 * t;
            if (r0 < M) {
                float2* cp = reinterpret_cast<float2*>(C + (size_t)r0 * F + c0);
                float2 o = *cp;
                o.x += acc[mt][nt][0];
                o.y += acc[mt][nt][1];
                *cp = o;
            }
            if (r1 < M) {
                float2* cp = reinterpret_cast<float2*>(C + (size_t)r1 * F + c0);
                float2 o = *cp;
                o.x += acc[mt][nt][2];
                o.y += acc[mt][nt][3];
                *cp = o;
            }
        }
    }
}

// ------------------------------- launcher ----------------------------------
extern "C" void kernel_launch(void* const* d_in, const int* in_sizes, int n_in,
                              void* d_out, int out_size)
{
    const float* x   = (const float*)d_in[0];
    const int*   ei1 = (const int*)  d_in[1];
    const float* ea1 = (const float*)d_in[2];
    const int*   ei2 = (const int*)  d_in[3];
    const float* ea2 = (const float*)d_in[4];

    const float* W[3][3];
    const float* Bv[3][3];
    for (int blk = 0; blk < 3; blk++)
        for (int p = 0; p < 3; p++) {
            W[blk][p]  = (const float*)d_in[5 + blk * 6 + p * 2];
            Bv[blk][p] = (const float*)d_in[5 + blk * 6 + p * 2 + 1];
        }

    const int Nn = in_sizes[0] / F;
    const int E1 = in_sizes[1] / 2;
    const int E2 = in_sizes[3] / 2;

    float *s1, *s2, *x1, *x2;
    int *off1, *cur1, *off2, *cur2, *part1, *part2;
    int2 *e1, *e2;
    cudaGetSymbolAddress((void**)&s1, g_s1);
    cudaGetSymbolAddress((void**)&s2, g_s2);
    cudaGetSymbolAddress((void**)&x1, g_x1);
    cudaGetSymbolAddress((void**)&x2, g_x2);
    cudaGetSymbolAddress((void**)&off1, g_off1);
    cudaGetSymbolAddress((void**)&cur1, g_cur1);
    cudaGetSymbolAddress((void**)&off2, g_off2);
    cudaGetSymbolAddress((void**)&cur2, g_cur2);
    cudaGetSymbolAddress((void**)&e1, g_e1);
    cudaGetSymbolAddress((void**)&e2, g_e2);
    cudaGetSymbolAddress((void**)&part1, g_part1);
    cudaGetSymbolAddress((void**)&part2, g_part2);

    const int NB = (Nn + 511) / 512;

    // ---- CSR build (once; edges constant across blocks) ----
    cudaMemsetAsync(cur1, 0, Nn * sizeof(int), 0);
    cudaMemsetAsync(cur2, 0, Nn * sizeof(int), 0);
    hist_dual<<<1024, 256>>>(ei1 + E1, E1, cur1, ei2 + E2, E2, cur2);
    {
        dim3 gA(NB, 2);
        scanA_kernel<<<gA, 512>>>(cur1, off1, part1, cur2, off2, part2, Nn);
        scanB_kernel<<<2, 512>>>(part1, part2, NB);
        dim3 gC(256, 2);
        scanC_kernel<<<gC, 256>>>(off1, part1, cur1, off2, part2, cur2, Nn);
    }
    fill_dual<<<1024, 256>>>(ei1, ei1 + E1, ea1, E1, cur1, e1,
                             ei2, ei2 + E2, ea2, E2, cur2, e2);
    // after fill: cur[i] == off[i] + degree(i) == row end

    float* outs[3] = {x1, x2, (float*)d_out};
    const float* xin = x;
    const int ggrid   = (Nn + 127) / 128;
    const int sgrid   = (2 * Nn + 15) / 16;
    const int kstride = (sgrid + ggrid - 1) / ggrid + 1;
    const int tgrid   = ggrid * kstride;

    for (int blk = 0; blk < 3; blk++) {
        mixed_gather_xw0<<<tgrid, 512>>>(
            (const float4*)xin,
            off1, cur1, e1, (float4*)s1,
            off2, cur2, e2, (float4*)s2,
            W[blk][0], Bv[blk][0], Bv[blk][1], Bv[blk][2],
            outs[blk], Nn, sgrid, kstride);
        gemm2_acc<<<ggrid, 256>>>(
            s1, s2, W[blk][1], W[blk][2], outs[blk], Nn);
        xin = outs[blk];
    }
}

// round 10
// speedup vs baseline: 1.3624x; 1.3624x over previous
#include <cuda_runtime.h>
#include <cuda_bf16.h>
#include <cstdint>

#define NMAX 100000
#define EMAX 1700000
#define F 128

// ------------------------- device-global scratch ---------------------------
__device__ float g_s1[(size_t)NMAX * F];
__device__ float g_s2[(size_t)NMAX * F];
__device__ float g_x1[(size_t)NMAX * F];
__device__ float g_x2[(size_t)NMAX * F];
__device__ int   g_off1[NMAX], g_cur1[NMAX];
__device__ int   g_off2[NMAX], g_cur2[NMAX];
__device__ int2  g_e1[EMAX], g_e2[EMAX];     // interleaved {src, w-bits}
__device__ int   g_part1[512], g_part2[512];

// ------------------------------- CSR build ---------------------------------
// dual-graph histogram, int4-vectorized
__global__ void hist_dual(const int* __restrict__ d1, int E1, int* __restrict__ c1,
                          const int* __restrict__ d2, int E2, int* __restrict__ c2)
{
    int i = blockIdx.x * blockDim.x + threadIdx.x;
    int stride = gridDim.x * blockDim.x;
    const int q1 = E1 >> 2, q2 = E2 >> 2;
    const int total = q1 + q2;
    for (int j = i; j < total; j += stride) {
        if (j < q1) {
            int4 v = __ldg((const int4*)d1 + j);
            atomicAdd(&c1[v.x], 1); atomicAdd(&c1[v.y], 1);
            atomicAdd(&c1[v.z], 1); atomicAdd(&c1[v.w], 1);
        } else {
            int4 v = __ldg((const int4*)d2 + (j - q1));
            atomicAdd(&c2[v.x], 1); atomicAdd(&c2[v.y], 1);
            atomicAdd(&c2[v.z], 1); atomicAdd(&c2[v.w], 1);
        }
    }
    if (i < (E1 & 3)) atomicAdd(&c1[d1[(q1 << 2) + i]], 1);
    else if (i >= 4 && i - 4 < (E2 & 3)) atomicAdd(&c2[d2[(q2 << 2) + i - 4]], 1);
}

__global__ void __launch_bounds__(512) scanA_kernel(
    const int* __restrict__ cnt1, int* __restrict__ off1, int* __restrict__ p1,
    const int* __restrict__ cnt2, int* __restrict__ off2, int* __restrict__ p2,
    int N)
{
    const int* cnt = blockIdx.y ? cnt2 : cnt1;
    int* off       = blockIdx.y ? off2 : off1;
    int* partial   = blockIdx.y ? p2   : p1;
    __shared__ int sh[512];
    int t = threadIdx.x;
    int i = blockIdx.x * 512 + t;
    int v = (i < N) ? cnt[i] : 0;
    sh[t] = v;
    __syncthreads();
#pragma unroll
    for (int d = 1; d < 512; d <<= 1) {
        int u = (t >= d) ? sh[t - d] : 0;
        __syncthreads();
        sh[t] += u;
        __syncthreads();
    }
    if (i < N) off[i] = sh[t] - v;
    if (t == 511) partial[blockIdx.x] = sh[511];
}

__global__ void __launch_bounds__(512) scanB_kernel(
    int* __restrict__ p1, int* __restrict__ p2, int NB)
{
    int* partial = blockIdx.x ? p2 : p1;
    __shared__ int sh[512];
    int t = threadIdx.x;
    int v = (t < NB) ? partial[t] : 0;
    sh[t] = v;
    __syncthreads();
#pragma unroll
    for (int d = 1; d < 512; d <<= 1) {
        int u = (t >= d) ? sh[t - d] : 0;
        __syncthreads();
        sh[t] += u;
        __syncthreads();
    }
    if (t < NB) partial[t] = sh[t] - v;
}

__global__ void scanC_kernel(int* __restrict__ off1, const int* __restrict__ p1,
                             int* __restrict__ cur1,
                             int* __restrict__ off2, const int* __restrict__ p2,
                             int* __restrict__ cur2, int N)
{
    int* off        = blockIdx.y ? off2 : off1;
    const int* pb   = blockIdx.y ? p2   : p1;
    int* cur        = blockIdx.y ? cur2 : cur1;
    int i = blockIdx.x * blockDim.x + threadIdx.x;
    int stride = gridDim.x * blockDim.x;
    for (; i < N; i += stride) {
        int o = off[i] + pb[i >> 9];
        off[i] = o;
        cur[i] = o;
    }
}

__global__ void fill_dual(
    const int* __restrict__ s1, const int* __restrict__ d1, const float* __restrict__ w1,
    int E1, int* __restrict__ c1, int2* __restrict__ eo1,
    const int* __restrict__ s2, const int* __restrict__ d2, const float* __restrict__ w2,
    int E2, int* __restrict__ c2, int2* __restrict__ eo2)
{
    int i = blockIdx.x * blockDim.x + threadIdx.x;
    int stride = gridDim.x * blockDim.x;
    const int q1 = E1 >> 2, q2 = E2 >> 2;
    const int total = q1 + q2;
    for (int j = i; j < total; j += stride) {
        if (j < q1) {
            int4   dv = __ldg((const int4*)d1 + j);
            int4   sv = __ldg((const int4*)s1 + j);
            float4 wv = __ldg((const float4*)w1 + j);
            int p;
            p = atomicAdd(&c1[dv.x], 1); eo1[p] = make_int2(sv.x, __float_as_int(wv.x));
            p = atomicAdd(&c1[dv.y], 1); eo1[p] = make_int2(sv.y, __float_as_int(wv.y));
            p = atomicAdd(&c1[dv.z], 1); eo1[p] = make_int2(sv.z, __float_as_int(wv.z));
            p = atomicAdd(&c1[dv.w], 1); eo1[p] = make_int2(sv.w, __float_as_int(wv.w));
        } else {
            int k = j - q1;
            int4   dv = __ldg((const int4*)d2 + k);
            int4   sv = __ldg((const int4*)s2 + k);
            float4 wv = __ldg((const float4*)w2 + k);
            int p;
            p = atomicAdd(&c2[dv.x], 1); eo2[p] = make_int2(sv.x, __float_as_int(wv.x));
            p = atomicAdd(&c2[dv.y], 1); eo2[p] = make_int2(sv.y, __float_as_int(wv.y));
            p = atomicAdd(&c2[dv.z], 1); eo2[p] = make_int2(sv.z, __float_as_int(wv.z));
            p = atomicAdd(&c2[dv.w], 1); eo2[p] = make_int2(sv.w, __float_as_int(wv.w));
        }
    }
    if (i < (E1 & 3)) {
        int k = (q1 << 2) + i;
        int p = atomicAdd(&c1[d1[k]], 1);
        eo1[p] = make_int2(s1[k], __float_as_int(w1[k]));
    } else if (i >= 4 && i - 4 < (E2 & 3)) {
        int k = (q2 << 2) + (i - 4);
        int p = atomicAdd(&c2[d2[k]], 1);
        eo2[p] = make_int2(s2[k], __float_as_int(w2[k]));
    }
}

// -------------------------- CSR gather SpMM ---------------------------------
// out[row] = sum_{edges} w * x[src]; warp per row, float4 per lane, MLP=8,
// smem-staged edge metadata with zero-weight padding (no tail loop). R4-exact.
__global__ void __launch_bounds__(512) spmm_gather(
    const float4* __restrict__ x4,
    const int* __restrict__ off, const int* __restrict__ end,
    const int2* __restrict__ edges,
    float4* __restrict__ out4, int N)
{
    __shared__ int2 se[16][32];

    const int wid  = threadIdx.x >> 5;
    const int lane = threadIdx.x & 31;
    const int row  = blockIdx.x * 16 + wid;
    if (row >= N) return;

    const int beg = __ldg(off + row);
    const int en  = __ldg(end + row);

    float4 acc = make_float4(0.f, 0.f, 0.f, 0.f);

    for (int j = beg; j < en; j += 32) {
        const int cnt = min(32, en - j);
        int2 e = make_int2(0, 0);                 // w = 0.0f pad -> contributes 0
        if (lane < cnt) e = __ldg(edges + j + lane);
        se[wid][lane] = e;
        __syncwarp();

        const int cnt8 = (cnt + 7) & ~7;
#pragma unroll 1
        for (int t = 0; t < cnt8; t += 8) {
            float4 v[8];
            float  w[8];
#pragma unroll
            for (int u = 0; u < 8; u++) {
                int2 ee = se[wid][t + u];
                w[u] = __int_as_float(ee.y);
                v[u] = __ldg(x4 + (size_t)ee.x * 32 + lane);
            }
#pragma unroll
            for (int u = 0; u < 8; u++) {
                acc.x += w[u] * v[u].x;
                acc.y += w[u] * v[u].y;
                acc.z += w[u] * v[u].z;
                acc.w += w[u] * v[u].w;
            }
        }
        __syncwarp();
    }
    out4[(size_t)row * 32 + lane] = acc;
}

// ---------------------- tensor-core fused 3-source GEMM ---------------------
__device__ __forceinline__ void ldsm_x4(uint32_t* r, uint32_t addr) {
    asm volatile("ldmatrix.sync.aligned.m8n8.x4.shared.b16 {%0,%1,%2,%3}, [%4];"
                 : "=r"(r[0]), "=r"(r[1]), "=r"(r[2]), "=r"(r[3]) : "r"(addr));
}
__device__ __forceinline__ void ldsm_x2t(uint32_t& r0, uint32_t& r1, uint32_t addr) {
    asm volatile("ldmatrix.sync.aligned.m8n8.x2.trans.shared.b16 {%0,%1}, [%2];"
                 : "=r"(r0), "=r"(r1) : "r"(addr));
}
__device__ __forceinline__ void mma_bf16(float* d, const uint32_t* a, uint32_t b0, uint32_t b1) {
    asm volatile("mma.sync.aligned.m16n8k16.row.col.f32.bf16.bf16.f32 "
                 "{%0,%1,%2,%3}, {%4,%5,%6,%7}, {%8,%9}, {%0,%1,%2,%3};"
                 : "+f"(d[0]), "+f"(d[1]), "+f"(d[2]), "+f"(d[3])
                 : "r"(a[0]), "r"(a[1]), "r"(a[2]), "r"(a[3]), "r"(b0), "r"(b1));
}

#define A_STRIDE 24

__global__ void __launch_bounds__(256, 2) gemm3_tc(
    const float* __restrict__ A0, const float* __restrict__ A1, const float* __restrict__ A2,
    const float* __restrict__ B0, const float* __restrict__ B1, const float* __restrict__ B2,
    const float* __restrict__ b0, const float* __restrict__ b1, const float* __restrict__ b2,
    float* __restrict__ C, int M)
{
    __shared__ __nv_bfloat16 Ahi[128 * A_STRIDE];
    __shared__ __nv_bfloat16 Alo[128 * A_STRIDE];
    __shared__ __nv_bfloat16 Bhi[16 * 128];
    __shared__ __nv_bfloat16 Blo[16 * 128];
    __shared__ float bsum[128];

    const int tid  = threadIdx.x;
    const int lane = tid & 31;
    const int wid  = tid >> 5;
    const int row0 = blockIdx.x * 128;

    const int wm = (wid >> 1) * 32;
    const int wn = (wid & 1) * 64;

    if (tid < 128) bsum[tid] = __ldg(b0 + tid) + __ldg(b1 + tid) + __ldg(b2 + tid);

    float acc[2][8][4];
#pragma unroll
    for (int mt = 0; mt < 2; mt++)
#pragma unroll
        for (int nt = 0; nt < 8; nt++)
#pragma unroll
            for (int q = 0; q < 4; q++) acc[mt][nt][q] = 0.f;

    const int alr   = tid >> 1;
    const int akoff = (tid & 1) * 8;
    const bool arow_ok = (row0 + alr) < M;
    const int bk = tid >> 4;
    const int bj = tid & 15;

    const uint32_t sAhi = (uint32_t)__cvta_generic_to_shared(Ahi);
    const uint32_t sAlo = (uint32_t)__cvta_generic_to_shared(Alo);
    const uint32_t sBhi = (uint32_t)__cvta_generic_to_shared(Bhi);
    const uint32_t sBlo = (uint32_t)__cvta_generic_to_shared(Blo);

    const float* Alist[3] = {A0, A1, A2};
    const float* Blist[3] = {B0, B1, B2};

    for (int s = 0; s < 3; s++) {
        const float* A = Alist[s];
        const float* B = Blist[s];

#pragma unroll 1
        for (int kk = 0; kk < 8; kk++) {
            const int k0 = kk * 16;
            __syncthreads();

            {
                float f[8] = {0, 0, 0, 0, 0, 0, 0, 0};
                if (arow_ok) {
                    const float* ap = A + (size_t)(row0 + alr) * F + k0 + akoff;
                    float4 fa = *reinterpret_cast<const float4*>(ap);
                    float4 fb = *reinterpret_cast<const float4*>(ap + 4);
                    f[0] = fa.x; f[1] = fa.y; f[2] = fa.z; f[3] = fa.w;
                    f[4] = fb.x; f[5] = fb.y; f[6] = fb.z; f[7] = fb.w;
                }
                union { __nv_bfloat16 b[8]; uint4 u; } H, L;
#pragma unroll
                for (int q = 0; q < 8; q++) {
                    H.b[q] = __float2bfloat16(f[q]);
                    L.b[q] = __float2bfloat16(f[q] - __bfloat162float(H.b[q]));
                }
                *reinterpret_cast<uint4*>(&Ahi[alr * A_STRIDE + akoff]) = H.u;
                *reinterpret_cast<uint4*>(&Alo[alr * A_STRIDE + akoff]) = L.u;
            }
            {
                const float* bp = B + (size_t)(k0 + bk) * F + bj * 8;
                float4 fa = *reinterpret_cast<const float4*>(bp);
                float4 fb = *reinterpret_cast<const float4*>(bp + 4);
                float f[8] = {fa.x, fa.y, fa.z, fa.w, fb.x, fb.y, fb.z, fb.w};
                union { __nv_bfloat16 b[8]; uint4 u; } H, L;
#pragma unroll
                for (int q = 0; q < 8; q++) {
                    H.b[q] = __float2bfloat16(f[q]);
                    L.b[q] = __float2bfloat16(f[q] - __bfloat162float(H.b[q]));
                }
                const int cpos = bk * 128 + ((bj ^ (bk & 7)) * 8);
                *reinterpret_cast<uint4*>(&Bhi[cpos]) = H.u;
                *reinterpret_cast<uint4*>(&Blo[cpos]) = L.u;
            }
            __syncthreads();

            uint32_t ahi[2][4], alo[2][4];
#pragma unroll
            for (int mt = 0; mt < 2; mt++) {
                const int rl = wm + mt * 16 + (lane & 15);
                const uint32_t aoff = (uint32_t)(rl * (A_STRIDE * 2)) + ((lane >> 4) << 4);
                ldsm_x4(ahi[mt], sAhi + aoff);
                ldsm_x4(alo[mt], sAlo + aoff);
            }
#pragma unroll
            for (int nt = 0; nt < 8; nt++) {
                const int kl = lane & 15;
                const int chunk = ((wn >> 3) + nt) ^ (kl & 7);
                const uint32_t boff = (uint32_t)(kl * 256) + (uint32_t)(chunk << 4);
                uint32_t bh0, bh1, bl0, bl1;
                ldsm_x2t(bh0, bh1, sBhi + boff);
                ldsm_x2t(bl0, bl1, sBlo + boff);
#pragma unroll
                for (int mt = 0; mt < 2; mt++) {
                    mma_bf16(acc[mt][nt], ahi[mt], bh0, bh1);
                    mma_bf16(acc[mt][nt], ahi[mt], bl0, bl1);
                    mma_bf16(acc[mt][nt], alo[mt], bh0, bh1);
                }
            }
        }
    }
    __syncthreads();

    const int g = lane >> 2;
    const int t = lane & 3;
#pragma unroll
    for (int mt = 0; mt < 2; mt++) {
        const int r0 = row0 + wm + mt * 16 + g;
        const int r1 = r0 + 8;
#pragma unroll
        for (int nt = 0; nt < 8; nt++) {
            const int c0 = wn + nt * 8 + 2 * t;
            const float bs0 = bsum[c0], bs1 = bsum[c0 + 1];
            if (r0 < M) {
                float2 v = make_float2(acc[mt][nt][0] + bs0, acc[mt][nt][1] + bs1);
                *reinterpret_cast<float2*>(C + (size_t)r0 * F + c0) = v;
            }
            if (r1 < M) {
                float2 v = make_float2(acc[mt][nt][2] + bs0, acc[mt][nt][3] + bs1);
                *reinterpret_cast<float2*>(C + (size_t)r1 * F + c0) = v;
            }
        }
    }
}

// ------------------------------- launcher ----------------------------------
extern "C" void kernel_launch(void* const* d_in, const int* in_sizes, int n_in,
                              void* d_out, int out_size)
{
    const float* x   = (const float*)d_in[0];
    const int*   ei1 = (const int*)  d_in[1];
    const float* ea1 = (const float*)d_in[2];
    const int*   ei2 = (const int*)  d_in[3];
    const float* ea2 = (const float*)d_in[4];

    const float* W[3][3];
    const float* Bv[3][3];
    for (int blk = 0; blk < 3; blk++)
        for (int p = 0; p < 3; p++) {
            W[blk][p]  = (const float*)d_in[5 + blk * 6 + p * 2];
            Bv[blk][p] = (const float*)d_in[5 + blk * 6 + p * 2 + 1];
        }

    const int Nn = in_sizes[0] / F;
    const int E1 = in_sizes[1] / 2;
    const int E2 = in_sizes[3] / 2;

    float *s1, *s2, *x1, *x2;
    int *off1, *cur1, *off2, *cur2, *part1, *part2;
    int2 *e1, *e2;
    cudaGetSymbolAddress((void**)&s1, g_s1);
    cudaGetSymbolAddress((void**)&s2, g_s2);
    cudaGetSymbolAddress((void**)&x1, g_x1);
    cudaGetSymbolAddress((void**)&x2, g_x2);
    cudaGetSymbolAddress((void**)&off1, g_off1);
    cudaGetSymbolAddress((void**)&cur1, g_cur1);
    cudaGetSymbolAddress((void**)&off2, g_off2);
    cudaGetSymbolAddress((void**)&cur2, g_cur2);
    cudaGetSymbolAddress((void**)&e1, g_e1);
    cudaGetSymbolAddress((void**)&e2, g_e2);
    cudaGetSymbolAddress((void**)&part1, g_part1);
    cudaGetSymbolAddress((void**)&part2, g_part2);

    const int NB = (Nn + 511) / 512;

    // ---- CSR build (once; edges constant across blocks) ----
    cudaMemsetAsync(cur1, 0, Nn * sizeof(int), 0);
    cudaMemsetAsync(cur2, 0, Nn * sizeof(int), 0);
    hist_dual<<<1024, 256>>>(ei1 + E1, E1, cur1, ei2 + E2, E2, cur2);
    {
        dim3 gA(NB, 2);
        scanA_kernel<<<gA, 512>>>(cur1, off1, part1, cur2, off2, part2, Nn);
        scanB_kernel<<<2, 512>>>(part1, part2, NB);
        dim3 gC(256, 2);
        scanC_kernel<<<gC, 256>>>(off1, part1, cur1, off2, part2, cur2, Nn);
    }
    fill_dual<<<1024, 256>>>(ei1, ei1 + E1, ea1, E1, cur1, e1,
                             ei2, ei2 + E2, ea2, E2, cur2, e2);
    // after fill: cur[i] == off[i] + degree(i) == row end

    float* outs[3] = {x1, x2, (float*)d_out};
    const float* xin = x;
    const int sgrid = (Nn + 15) / 16;
    const int ggrid = (Nn + 127) / 128;

    for (int blk = 0; blk < 3; blk++) {
        spmm_gather<<<sgrid, 512>>>((const float4*)xin, off1, cur1, e1,
                                    (float4*)s1, Nn);
        spmm_gather<<<sgrid, 512>>>((const float4*)xin, off2, cur2, e2,
                                    (float4*)s2, Nn);
        gemm3_tc<<<ggrid, 256>>>(
            xin, s1, s2,
            W[blk][0], W[blk][1], W[blk][2],
            Bv[blk][0], Bv[blk][1], Bv[blk][2],
            outs[blk], Nn);
        xin = outs[blk];
    }
}

// round 11
// speedup vs baseline: 1.4068x; 1.0326x over previous
#include <cuda_runtime.h>
#include <cuda_bf16.h>
#include <cuda_fp16.h>
#include <cstdint>

#define NMAX 100000
#define EMAX 1700000
#define F 128

// ------------------------- device-global scratch ---------------------------
__device__ float  g_s1[(size_t)NMAX * F];
__device__ float  g_s2[(size_t)NMAX * F];
__device__ float  g_x1[(size_t)NMAX * F];
__device__ float  g_x2[(size_t)NMAX * F];
__device__ __half g_xh[(size_t)NMAX * F];    // fp16 mirror of current layer input
__device__ int    g_off1[NMAX], g_cur1[NMAX];
__device__ int    g_off2[NMAX], g_cur2[NMAX];
__device__ int2   g_e1[EMAX], g_e2[EMAX];    // interleaved {src, w-bits}
__device__ int    g_part1[512], g_part2[512];

// ------------------------------- CSR build ---------------------------------
__global__ void hist_dual(const int* __restrict__ d1, int E1, int* __restrict__ c1,
                          const int* __restrict__ d2, int E2, int* __restrict__ c2)
{
    int i = blockIdx.x * blockDim.x + threadIdx.x;
    int stride = gridDim.x * blockDim.x;
    int total = E1 + E2;
    for (; i < total; i += stride) {
        if (i < E1) atomicAdd(&c1[d1[i]], 1);
        else        atomicAdd(&c2[d2[i - E1]], 1);
    }
}

__global__ void __launch_bounds__(512) scanA_kernel(
    const int* __restrict__ cnt1, int* __restrict__ off1, int* __restrict__ p1,
    const int* __restrict__ cnt2, int* __restrict__ off2, int* __restrict__ p2,
    int N)
{
    const int* cnt = blockIdx.y ? cnt2 : cnt1;
    int* off       = blockIdx.y ? off2 : off1;
    int* partial   = blockIdx.y ? p2   : p1;
    __shared__ int sh[512];
    int t = threadIdx.x;
    int i = blockIdx.x * 512 + t;
    int v = (i < N) ? cnt[i] : 0;
    sh[t] = v;
    __syncthreads();
#pragma unroll
    for (int d = 1; d < 512; d <<= 1) {
        int u = (t >= d) ? sh[t - d] : 0;
        __syncthreads();
        sh[t] += u;
        __syncthreads();
    }
    if (i < N) off[i] = sh[t] - v;
    if (t == 511) partial[blockIdx.x] = sh[511];
}

__global__ void __launch_bounds__(512) scanB_kernel(
    int* __restrict__ p1, int* __restrict__ p2, int NB)
{
    int* partial = blockIdx.x ? p2 : p1;
    __shared__ int sh[512];
    int t = threadIdx.x;
    int v = (t < NB) ? partial[t] : 0;
    sh[t] = v;
    __syncthreads();
#pragma unroll
    for (int d = 1; d < 512; d <<= 1) {
        int u = (t >= d) ? sh[t - d] : 0;
        __syncthreads();
        sh[t] += u;
        __syncthreads();
    }
    if (t < NB) partial[t] = sh[t] - v;
}

__global__ void scanC_kernel(int* __restrict__ off1, const int* __restrict__ p1,
                             int* __restrict__ cur1,
                             int* __restrict__ off2, const int* __restrict__ p2,
                             int* __restrict__ cur2, int N)
{
    int* off        = blockIdx.y ? off2 : off1;
    const int* pb   = blockIdx.y ? p2   : p1;
    int* cur        = blockIdx.y ? cur2 : cur1;
    int i = blockIdx.x * blockDim.x + threadIdx.x;
    int stride = gridDim.x * blockDim.x;
    for (; i < N; i += stride) {
        int o = off[i] + pb[i >> 9];
        off[i] = o;
        cur[i] = o;
    }
}

__global__ void fill_dual(
    const int* __restrict__ s1, const int* __restrict__ d1, const float* __restrict__ w1,
    int E1, int* __restrict__ c1, int2* __restrict__ eo1,
    const int* __restrict__ s2, const int* __restrict__ d2, const float* __restrict__ w2,
    int E2, int* __restrict__ c2, int2* __restrict__ eo2)
{
    int i = blockIdx.x * blockDim.x + threadIdx.x;
    int stride = gridDim.x * blockDim.x;
    int total = E1 + E2;
    for (; i < total; i += stride) {
        if (i < E1) {
            int p = atomicAdd(&c1[d1[i]], 1);
            eo1[p] = make_int2(s1[i], __float_as_int(w1[i]));
        } else {
            int k = i - E1;
            int p = atomicAdd(&c2[d2[k]], 1);
            eo2[p] = make_int2(s2[k], __float_as_int(w2[k]));
        }
    }
}

// -------------------------- fp32 -> fp16 mirror ------------------------------
__global__ void f32_to_f16(const float4* __restrict__ x, uint2* __restrict__ out, int n4)
{
    int i = blockIdx.x * blockDim.x + threadIdx.x;
    int stride = gridDim.x * blockDim.x;
    for (; i < n4; i += stride) {
        float4 v = __ldg(x + i);
        __half2 h0 = __floats2half2_rn(v.x, v.y);
        __half2 h1 = __floats2half2_rn(v.z, v.w);
        out[i] = make_uint2(*(uint32_t*)&h0, *(uint32_t*)&h1);
    }
}

// -------------------------- CSR gather SpMM (fp16 x) -------------------------
// out[row] = sum_{edges} w * xh[src]; warp per row, 4 halves per lane, MLP=8,
// smem-staged edge metadata with zero-weight padding (R4 structure).
__global__ void __launch_bounds__(512) spmm_gather(
    const uint2* __restrict__ xh,            // [N*32], each uint2 = 4 fp16
    const int* __restrict__ off, const int* __restrict__ end,
    const int2* __restrict__ edges,
    float4* __restrict__ out4, int N)
{
    __shared__ int2 se[16][32];

    const int wid  = threadIdx.x >> 5;
    const int lane = threadIdx.x & 31;
    const int row  = blockIdx.x * 16 + wid;
    if (row >= N) return;

    const int beg = __ldg(off + row);
    const int en  = __ldg(end + row);

    float4 acc = make_float4(0.f, 0.f, 0.f, 0.f);

    for (int j = beg; j < en; j += 32) {
        const int cnt = min(32, en - j);
        int2 e = make_int2(0, 0);                 // w = 0.0f pad -> contributes 0
        if (lane < cnt) e = __ldg(edges + j + lane);
        se[wid][lane] = e;
        __syncwarp();

        const int cnt8 = (cnt + 7) & ~7;
#pragma unroll 1
        for (int t = 0; t < cnt8; t += 8) {
            uint2 raw[8];
            float w[8];
#pragma unroll
            for (int u = 0; u < 8; u++) {
                int2 ee = se[wid][t + u];
                w[u] = __int_as_float(ee.y);
                raw[u] = __ldg(xh + (size_t)ee.x * 32 + lane);
            }
#pragma unroll
            for (int u = 0; u < 8; u++) {
                float2 a = __half22float2(*reinterpret_cast<__half2*>(&raw[u].x));
                float2 b = __half22float2(*reinterpret_cast<__half2*>(&raw[u].y));
                acc.x += w[u] * a.x;
                acc.y += w[u] * a.y;
                acc.z += w[u] * b.x;
                acc.w += w[u] * b.y;
            }
        }
        __syncwarp();
    }
    out4[(size_t)row * 32 + lane] = acc;
}

// ---------------------- tensor-core fused 3-source GEMM ---------------------
__device__ __forceinline__ void ldsm_x4(uint32_t* r, uint32_t addr) {
    asm volatile("ldmatrix.sync.aligned.m8n8.x4.shared.b16 {%0,%1,%2,%3}, [%4];"
                 : "=r"(r[0]), "=r"(r[1]), "=r"(r[2]), "=r"(r[3]) : "r"(addr));
}
__device__ __forceinline__ void ldsm_x2t(uint32_t& r0, uint32_t& r1, uint32_t addr) {
    asm volatile("ldmatrix.sync.aligned.m8n8.x2.trans.shared.b16 {%0,%1}, [%2];"
                 : "=r"(r0), "=r"(r1) : "r"(addr));
}
__device__ __forceinline__ void mma_bf16(float* d, const uint32_t* a, uint32_t b0, uint32_t b1) {
    asm volatile("mma.sync.aligned.m16n8k16.row.col.f32.bf16.bf16.f32 "
                 "{%0,%1,%2,%3}, {%4,%5,%6,%7}, {%8,%9}, {%0,%1,%2,%3};"
                 : "+f"(d[0]), "+f"(d[1]), "+f"(d[2]), "+f"(d[3])
                 : "r"(a[0]), "r"(a[1]), "r"(a[2]), "r"(a[3]), "r"(b0), "r"(b1));
}

#define A_STRIDE 24

__global__ void __launch_bounds__(256, 2) gemm3_tc(
    const float* __restrict__ A0, const float* __restrict__ A1, const float* __restrict__ A2,
    const float* __restrict__ B0, const float* __restrict__ B1, const float* __restrict__ B2,
    const float* __restrict__ b0, const float* __restrict__ b1, const float* __restrict__ b2,
    float* __restrict__ C, __half* __restrict__ Ch, int writeh, int M)
{
    __shared__ __nv_bfloat16 Ahi[128 * A_STRIDE];
    __shared__ __nv_bfloat16 Alo[128 * A_STRIDE];
    __shared__ __nv_bfloat16 Bhi[16 * 128];
    __shared__ __nv_bfloat16 Blo[16 * 128];
    __shared__ float bsum[128];

    const int tid  = threadIdx.x;
    const int lane = tid & 31;
    const int wid  = tid >> 5;
    const int row0 = blockIdx.x * 128;

    const int wm = (wid >> 1) * 32;
    const int wn = (wid & 1) * 64;

    if (tid < 128) bsum[tid] = __ldg(b0 + tid) + __ldg(b1 + tid) + __ldg(b2 + tid);

    float acc[2][8][4];
#pragma unroll
    for (int mt = 0; mt < 2; mt++)
#pragma unroll
        for (int nt = 0; nt < 8; nt++)
#pragma unroll
            for (int q = 0; q < 4; q++) acc[mt][nt][q] = 0.f;

    const int alr   = tid >> 1;
    const int akoff = (tid & 1) * 8;
    const bool arow_ok = (row0 + alr) < M;
    const int bk = tid >> 4;
    const int bj = tid & 15;

    const uint32_t sAhi = (uint32_t)__cvta_generic_to_shared(Ahi);
    const uint32_t sAlo = (uint32_t)__cvta_generic_to_shared(Alo);
    const uint32_t sBhi = (uint32_t)__cvta_generic_to_shared(Bhi);
    const uint32_t sBlo = (uint32_t)__cvta_generic_to_shared(Blo);

    const float* Alist[3] = {A0, A1, A2};
    const float* Blist[3] = {B0, B1, B2};

    for (int s = 0; s < 3; s++) {
        const float* A = Alist[s];
        const float* B = Blist[s];

#pragma unroll 1
        for (int kk = 0; kk < 8; kk++) {
            const int k0 = kk * 16;
            __syncthreads();

            {
                float f[8] = {0, 0, 0, 0, 0, 0, 0, 0};
                if (arow_ok) {
                    const float* ap = A + (size_t)(row0 + alr) * F + k0 + akoff;
                    float4 fa = *reinterpret_cast<const float4*>(ap);
                    float4 fb = *reinterpret_cast<const float4*>(ap + 4);
                    f[0] = fa.x; f[1] = fa.y; f[2] = fa.z; f[3] = fa.w;
                    f[4] = fb.x; f[5] = fb.y; f[6] = fb.z; f[7] = fb.w;
                }
                union { __nv_bfloat16 b[8]; uint4 u; } H, L;
#pragma unroll
                for (int q = 0; q < 8; q++) {
                    H.b[q] = __float2bfloat16(f[q]);
                    L.b[q] = __float2bfloat16(f[q] - __bfloat162float(H.b[q]));
                }
                *reinterpret_cast<uint4*>(&Ahi[alr * A_STRIDE + akoff]) = H.u;
                *reinterpret_cast<uint4*>(&Alo[alr * A_STRIDE + akoff]) = L.u;
            }
            {
                const float* bp = B + (size_t)(k0 + bk) * F + bj * 8;
                float4 fa = *reinterpret_cast<const float4*>(bp);
                float4 fb = *reinterpret_cast<const float4*>(bp + 4);
                float f[8] = {fa.x, fa.y, fa.z, fa.w, fb.x, fb.y, fb.z, fb.w};
                union { __nv_bfloat16 b[8]; uint4 u; } H, L;
#pragma unroll
                for (int q = 0; q < 8; q++) {
                    H.b[q] = __float2bfloat16(f[q]);
                    L.b[q] = __float2bfloat16(f[q] - __bfloat162float(H.b[q]));
                }
                const int cpos = bk * 128 + ((bj ^ (bk & 7)) * 8);
                *reinterpret_cast<uint4*>(&Bhi[cpos]) = H.u;
                *reinterpret_cast<uint4*>(&Blo[cpos]) = L.u;
            }
            __syncthreads();

            uint32_t ahi[2][4], alo[2][4];
#pragma unroll
            for (int mt = 0; mt < 2; mt++) {
                const int rl = wm + mt * 16 + (lane & 15);
                const uint32_t aoff = (uint32_t)(rl * (A_STRIDE * 2)) + ((lane >> 4) << 4);
                ldsm_x4(ahi[mt], sAhi + aoff);
                ldsm_x4(alo[mt], sAlo + aoff);
            }
#pragma unroll
            for (int nt = 0; nt < 8; nt++) {
                const int kl = lane & 15;
                const int chunk = ((wn >> 3) + nt) ^ (kl & 7);
                const uint32_t boff = (uint32_t)(kl * 256) + (uint32_t)(chunk << 4);
                uint32_t bh0, bh1, bl0, bl1;
                ldsm_x2t(bh0, bh1, sBhi + boff);
                ldsm_x2t(bl0, bl1, sBlo + boff);
#pragma unroll
                for (int mt = 0; mt < 2; mt++) {
                    mma_bf16(acc[mt][nt], ahi[mt], bh0, bh1);
                    mma_bf16(acc[mt][nt], ahi[mt], bl0, bl1);
                    mma_bf16(acc[mt][nt], alo[mt], bh0, bh1);
                }
            }
        }
    }
    __syncthreads();

    const int g = lane >> 2;
    const int t = lane & 3;
#pragma unroll
    for (int mt = 0; mt < 2; mt++) {
        const int r0 = row0 + wm + mt * 16 + g;
        const int r1 = r0 + 8;
#pragma unroll
        for (int nt = 0; nt < 8; nt++) {
            const int c0 = wn + nt * 8 + 2 * t;
            const float bs0 = bsum[c0], bs1 = bsum[c0 + 1];
            if (r0 < M) {
                float2 v = make_float2(acc[mt][nt][0] + bs0, acc[mt][nt][1] + bs1);
                *reinterpret_cast<float2*>(C + (size_t)r0 * F + c0) = v;
                if (writeh) {
                    __half2 hv = __floats2half2_rn(v.x, v.y);
                    *reinterpret_cast<__half2*>(Ch + (size_t)r0 * F + c0) = hv;
                }
            }
            if (r1 < M) {
                float2 v = make_float2(acc[mt][nt][2] + bs0, acc[mt][nt][3] + bs1);
                *reinterpret_cast<float2*>(C + (size_t)r1 * F + c0) = v;
                if (writeh) {
                    __half2 hv = __floats2half2_rn(v.x, v.y);
                    *reinterpret_cast<__half2*>(Ch + (size_t)r1 * F + c0) = hv;
                }
            }
        }
    }
}

// ------------------------------- launcher ----------------------------------
extern "C" void kernel_launch(void* const* d_in, const int* in_sizes, int n_in,
                              void* d_out, int out_size)
{
    const float* x   = (const float*)d_in[0];
    const int*   ei1 = (const int*)  d_in[1];
    const float* ea1 = (const float*)d_in[2];
    const int*   ei2 = (const int*)  d_in[3];
    const float* ea2 = (const float*)d_in[4];

    const float* W[3][3];
    const float* Bv[3][3];
    for (int blk = 0; blk < 3; blk++)
        for (int p = 0; p < 3; p++) {
            W[blk][p]  = (const float*)d_in[5 + blk * 6 + p * 2];
            Bv[blk][p] = (const float*)d_in[5 + blk * 6 + p * 2 + 1];
        }

    const int Nn = in_sizes[0] / F;
    const int E1 = in_sizes[1] / 2;
    const int E2 = in_sizes[3] / 2;

    float *s1, *s2, *x1, *x2;
    __half* xh;
    int *off1, *cur1, *off2, *cur2, *part1, *part2;
    int2 *e1, *e2;
    cudaGetSymbolAddress((void**)&s1, g_s1);
    cudaGetSymbolAddress((void**)&s2, g_s2);
    cudaGetSymbolAddress((void**)&x1, g_x1);
    cudaGetSymbolAddress((void**)&x2, g_x2);
    cudaGetSymbolAddress((void**)&xh, g_xh);
    cudaGetSymbolAddress((void**)&off1, g_off1);
    cudaGetSymbolAddress((void**)&cur1, g_cur1);
    cudaGetSymbolAddress((void**)&off2, g_off2);
    cudaGetSymbolAddress((void**)&cur2, g_cur2);
    cudaGetSymbolAddress((void**)&e1, g_e1);
    cudaGetSymbolAddress((void**)&e2, g_e2);
    cudaGetSymbolAddress((void**)&part1, g_part1);
    cudaGetSymbolAddress((void**)&part2, g_part2);

    const int NB = (Nn + 511) / 512;

    // ---- CSR build + fp16 mirror of x (edges constant across blocks) ----
    cudaMemsetAsync(cur1, 0, Nn * sizeof(int), 0);
    cudaMemsetAsync(cur2, 0, Nn * sizeof(int), 0);
    f32_to_f16<<<1024, 256>>>((const float4*)x, (uint2*)xh, Nn * 32);
    hist_dual<<<2048, 256>>>(ei1 + E1, E1, cur1, ei2 + E2, E2, cur2);
    {
        dim3 gA(NB, 2);
        scanA_kernel<<<gA, 512>>>(cur1, off1, part1, cur2, off2, part2, Nn);
        scanB_kernel<<<2, 512>>>(part1, part2, NB);
        dim3 gC(256, 2);
        scanC_kernel<<<gC, 256>>>(off1, part1, cur1, off2, part2, cur2, Nn);
    }
    fill_dual<<<2048, 256>>>(ei1, ei1 + E1, ea1, E1, cur1, e1,
                             ei2, ei2 + E2, ea2, E2, cur2, e2);
    // after fill: cur[i] == off[i] + degree(i) == row end

    float* outs[3] = {x1, x2, (float*)d_out};
    const float* xin = x;
    const int sgrid = (Nn + 15) / 16;
    const int ggrid = (Nn + 127) / 128;

    for (int blk = 0; blk < 3; blk++) {
        spmm_gather<<<sgrid, 512>>>((const uint2*)xh, off1, cur1, e1,
                                    (float4*)s1, Nn);
        spmm_gather<<<sgrid, 512>>>((const uint2*)xh, off2, cur2, e2,
                                    (float4*)s2, Nn);
        gemm3_tc<<<ggrid, 256>>>(
            xin, s1, s2,
            W[blk][0], W[blk][1], W[blk][2],
            Bv[blk][0], Bv[blk][1], Bv[blk][2],
            outs[blk], xh, (blk < 2) ? 1 : 0, Nn);
        xin = outs[blk];
    }
}

// round 12
// speedup vs baseline: 1.5521x; 1.1033x over previous
#include <cuda_runtime.h>
#include <cuda_bf16.h>
#include <cuda_fp16.h>
#include <cstdint>

#define NMAX 100000
#define EMAX 1700000
#define F 128

// ------------------------- device-global scratch ---------------------------
__device__ __half g_s1h[(size_t)NMAX * F];   // fp16 gathered s1
__device__ __half g_s2h[(size_t)NMAX * F];   // fp16 gathered s2
__device__ float  g_x1[(size_t)NMAX * F];
__device__ float  g_x2[(size_t)NMAX * F];
__device__ __half g_xh[(size_t)NMAX * F];    // fp16 mirror of current layer input
__device__ int    g_off1[NMAX], g_cur1[NMAX];
__device__ int    g_off2[NMAX], g_cur2[NMAX];
__device__ int2   g_e1[EMAX], g_e2[EMAX];    // interleaved {src, w-bits}
__device__ int    g_part1[512], g_part2[512];

// ------------------------------- CSR build ---------------------------------
__global__ void hist_dual(const int* __restrict__ d1, int E1, int* __restrict__ c1,
                          const int* __restrict__ d2, int E2, int* __restrict__ c2)
{
    int i = blockIdx.x * blockDim.x + threadIdx.x;
    int stride = gridDim.x * blockDim.x;
    int total = E1 + E2;
    for (; i < total; i += stride) {
        if (i < E1) atomicAdd(&c1[d1[i]], 1);
        else        atomicAdd(&c2[d2[i - E1]], 1);
    }
}

__global__ void __launch_bounds__(512) scanA_kernel(
    const int* __restrict__ cnt1, int* __restrict__ off1, int* __restrict__ p1,
    const int* __restrict__ cnt2, int* __restrict__ off2, int* __restrict__ p2,
    int N)
{
    const int* cnt = blockIdx.y ? cnt2 : cnt1;
    int* off       = blockIdx.y ? off2 : off1;
    int* partial   = blockIdx.y ? p2   : p1;
    __shared__ int sh[512];
    int t = threadIdx.x;
    int i = blockIdx.x * 512 + t;
    int v = (i < N) ? cnt[i] : 0;
    sh[t] = v;
    __syncthreads();
#pragma unroll
    for (int d = 1; d < 512; d <<= 1) {
        int u = (t >= d) ? sh[t - d] : 0;
        __syncthreads();
        sh[t] += u;
        __syncthreads();
    }
    if (i < N) off[i] = sh[t] - v;
    if (t == 511) partial[blockIdx.x] = sh[511];
}

__global__ void __launch_bounds__(512) scanB_kernel(
    int* __restrict__ p1, int* __restrict__ p2, int NB)
{
    int* partial = blockIdx.x ? p2 : p1;
    __shared__ int sh[512];
    int t = threadIdx.x;
    int v = (t < NB) ? partial[t] : 0;
    sh[t] = v;
    __syncthreads();
#pragma unroll
    for (int d = 1; d < 512; d <<= 1) {
        int u = (t >= d) ? sh[t - d] : 0;
        __syncthreads();
        sh[t] += u;
        __syncthreads();
    }
    if (t < NB) partial[t] = sh[t] - v;
}

__global__ void scanC_kernel(int* __restrict__ off1, const int* __restrict__ p1,
                             int* __restrict__ cur1,
                             int* __restrict__ off2, const int* __restrict__ p2,
                             int* __restrict__ cur2, int N)
{
    int* off        = blockIdx.y ? off2 : off1;
    const int* pb   = blockIdx.y ? p2   : p1;
    int* cur        = blockIdx.y ? cur2 : cur1;
    int i = blockIdx.x * blockDim.x + threadIdx.x;
    int stride = gridDim.x * blockDim.x;
    for (; i < N; i += stride) {
        int o = off[i] + pb[i >> 9];
        off[i] = o;
        cur[i] = o;
    }
}

__global__ void fill_dual(
    const int* __restrict__ s1, const int* __restrict__ d1, const float* __restrict__ w1,
    int E1, int* __restrict__ c1, int2* __restrict__ eo1,
    const int* __restrict__ s2, const int* __restrict__ d2, const float* __restrict__ w2,
    int E2, int* __restrict__ c2, int2* __restrict__ eo2)
{
    int i = blockIdx.x * blockDim.x + threadIdx.x;
    int stride = gridDim.x * blockDim.x;
    int total = E1 + E2;
    for (; i < total; i += stride) {
        if (i < E1) {
            int p = atomicAdd(&c1[d1[i]], 1);
            eo1[p] = make_int2(s1[i], __float_as_int(w1[i]));
        } else {
            int k = i - E1;
            int p = atomicAdd(&c2[d2[k]], 1);
            eo2[p] = make_int2(s2[k], __float_as_int(w2[k]));
        }
    }
}

// -------------------------- fp32 -> fp16 mirror ------------------------------
__global__ void f32_to_f16(const float4* __restrict__ x, uint2* __restrict__ out, int n4)
{
    int i = blockIdx.x * blockDim.x + threadIdx.x;
    int stride = gridDim.x * blockDim.x;
    for (; i < n4; i += stride) {
        float4 v = __ldg(x + i);
        __half2 h0 = __floats2half2_rn(v.x, v.y);
        __half2 h1 = __floats2half2_rn(v.z, v.w);
        out[i] = make_uint2(*(uint32_t*)&h0, *(uint32_t*)&h1);
    }
}

// -------------------------- CSR gather SpMM (fp16 in/out) --------------------
// out[row] = sum_{edges} w * xh[src]; warp per row, 4 halves per lane, MLP=8,
// smem-staged edge metadata with zero-weight padding. fp32 accumulate, fp16 out.
__global__ void __launch_bounds__(512) spmm_gather(
    const uint2* __restrict__ xh,            // [N*32], each uint2 = 4 fp16
    const int* __restrict__ off, const int* __restrict__ end,
    const int2* __restrict__ edges,
    uint2* __restrict__ outh, int N)         // fp16 out, 4 halves per lane
{
    __shared__ int2 se[16][32];

    const int wid  = threadIdx.x >> 5;
    const int lane = threadIdx.x & 31;
    const int row  = blockIdx.x * 16 + wid;
    if (row >= N) return;

    const int beg = __ldg(off + row);
    const int en  = __ldg(end + row);

    float4 acc = make_float4(0.f, 0.f, 0.f, 0.f);

    for (int j = beg; j < en; j += 32) {
        const int cnt = min(32, en - j);
        int2 e = make_int2(0, 0);                 // w = 0.0f pad -> contributes 0
        if (lane < cnt) e = __ldg(edges + j + lane);
        se[wid][lane] = e;
        __syncwarp();

        const int cnt8 = (cnt + 7) & ~7;
#pragma unroll 1
        for (int t = 0; t < cnt8; t += 8) {
            uint2 raw[8];
            float w[8];
#pragma unroll
            for (int u = 0; u < 8; u++) {
                int2 ee = se[wid][t + u];
                w[u] = __int_as_float(ee.y);
                raw[u] = __ldg(xh + (size_t)ee.x * 32 + lane);
            }
#pragma unroll
            for (int u = 0; u < 8; u++) {
                float2 a = __half22float2(*reinterpret_cast<__half2*>(&raw[u].x));
                float2 b = __half22float2(*reinterpret_cast<__half2*>(&raw[u].y));
                acc.x += w[u] * a.x;
                acc.y += w[u] * a.y;
                acc.z += w[u] * b.x;
                acc.w += w[u] * b.y;
            }
        }
        __syncwarp();
    }
    __half2 h0 = __floats2half2_rn(acc.x, acc.y);
    __half2 h1 = __floats2half2_rn(acc.z, acc.w);
    outh[(size_t)row * 32 + lane] = make_uint2(*(uint32_t*)&h0, *(uint32_t*)&h1);
}

// ---------------------- tensor-core fused 3-source GEMM ---------------------
// A0 fp32 (x), A1/A2 fp16 (s1,s2). C fp32 out; optional fp16 mirror for the
// next layer's gather.
__device__ __forceinline__ void ldsm_x4(uint32_t* r, uint32_t addr) {
    asm volatile("ldmatrix.sync.aligned.m8n8.x4.shared.b16 {%0,%1,%2,%3}, [%4];"
                 : "=r"(r[0]), "=r"(r[1]), "=r"(r[2]), "=r"(r[3]) : "r"(addr));
}
__device__ __forceinline__ void ldsm_x2t(uint32_t& r0, uint32_t& r1, uint32_t addr) {
    asm volatile("ldmatrix.sync.aligned.m8n8.x2.trans.shared.b16 {%0,%1}, [%2];"
                 : "=r"(r0), "=r"(r1) : "r"(addr));
}
__device__ __forceinline__ void mma_bf16(float* d, const uint32_t* a, uint32_t b0, uint32_t b1) {
    asm volatile("mma.sync.aligned.m16n8k16.row.col.f32.bf16.bf16.f32 "
                 "{%0,%1,%2,%3}, {%4,%5,%6,%7}, {%8,%9}, {%0,%1,%2,%3};"
                 : "+f"(d[0]), "+f"(d[1]), "+f"(d[2]), "+f"(d[3])
                 : "r"(a[0]), "r"(a[1]), "r"(a[2]), "r"(a[3]), "r"(b0), "r"(b1));
}

#define A_STRIDE 24

__global__ void __launch_bounds__(256, 2) gemm3_tc(
    const float* __restrict__ A0,
    const __half* __restrict__ A1, const __half* __restrict__ A2,
    const float* __restrict__ B0, const float* __restrict__ B1, const float* __restrict__ B2,
    const float* __restrict__ b0, const float* __restrict__ b1, const float* __restrict__ b2,
    float* __restrict__ C, __half* __restrict__ Ch, int writeh, int M)
{
    __shared__ __nv_bfloat16 Ahi[128 * A_STRIDE];
    __shared__ __nv_bfloat16 Alo[128 * A_STRIDE];
    __shared__ __nv_bfloat16 Bhi[16 * 128];
    __shared__ __nv_bfloat16 Blo[16 * 128];
    __shared__ float bsum[128];

    const int tid  = threadIdx.x;
    const int lane = tid & 31;
    const int wid  = tid >> 5;
    const int row0 = blockIdx.x * 128;

    const int wm = (wid >> 1) * 32;
    const int wn = (wid & 1) * 64;

    if (tid < 128) bsum[tid] = __ldg(b0 + tid) + __ldg(b1 + tid) + __ldg(b2 + tid);

    float acc[2][8][4];
#pragma unroll
    for (int mt = 0; mt < 2; mt++)
#pragma unroll
        for (int nt = 0; nt < 8; nt++)
#pragma unroll
            for (int q = 0; q < 4; q++) acc[mt][nt][q] = 0.f;

    const int alr   = tid >> 1;
    const int akoff = (tid & 1) * 8;
    const bool arow_ok = (row0 + alr) < M;
    const int bk = tid >> 4;
    const int bj = tid & 15;

    const uint32_t sAhi = (uint32_t)__cvta_generic_to_shared(Ahi);
    const uint32_t sAlo = (uint32_t)__cvta_generic_to_shared(Alo);
    const uint32_t sBhi = (uint32_t)__cvta_generic_to_shared(Bhi);
    const uint32_t sBlo = (uint32_t)__cvta_generic_to_shared(Blo);

    const float* Blist[3] = {B0, B1, B2};

    for (int s = 0; s < 3; s++) {
        const float* B = Blist[s];

#pragma unroll 1
        for (int kk = 0; kk < 8; kk++) {
            const int k0 = kk * 16;
            __syncthreads();

            {
                float f[8] = {0, 0, 0, 0, 0, 0, 0, 0};
                if (arow_ok) {
                    if (s == 0) {
                        const float* ap = A0 + (size_t)(row0 + alr) * F + k0 + akoff;
                        float4 fa = *reinterpret_cast<const float4*>(ap);
                        float4 fb = *reinterpret_cast<const float4*>(ap + 4);
                        f[0] = fa.x; f[1] = fa.y; f[2] = fa.z; f[3] = fa.w;
                        f[4] = fb.x; f[5] = fb.y; f[6] = fb.z; f[7] = fb.w;
                    } else {
                        const __half* ap = (s == 1 ? A1 : A2)
                                           + (size_t)(row0 + alr) * F + k0 + akoff;
                        uint4 hv = *reinterpret_cast<const uint4*>(ap);
                        float2 p0 = __half22float2(*reinterpret_cast<__half2*>(&hv.x));
                        float2 p1 = __half22float2(*reinterpret_cast<__half2*>(&hv.y));
                        float2 p2 = __half22float2(*reinterpret_cast<__half2*>(&hv.z));
                        float2 p3 = __half22float2(*reinterpret_cast<__half2*>(&hv.w));
                        f[0] = p0.x; f[1] = p0.y; f[2] = p1.x; f[3] = p1.y;
                        f[4] = p2.x; f[5] = p2.y; f[6] = p3.x; f[7] = p3.y;
                    }
                }
                union { __nv_bfloat16 b[8]; uint4 u; } H, L;
#pragma unroll
                for (int q = 0; q < 8; q++) {
                    H.b[q] = __float2bfloat16(f[q]);
                    L.b[q] = __float2bfloat16(f[q] - __bfloat162float(H.b[q]));
                }
                *reinterpret_cast<uint4*>(&Ahi[alr * A_STRIDE + akoff]) = H.u;
                *reinterpret_cast<uint4*>(&Alo[alr * A_STRIDE + akoff]) = L.u;
            }
            {
                const float* bp = B + (size_t)(k0 + bk) * F + bj * 8;
                float4 fa = *reinterpret_cast<const float4*>(bp);
                float4 fb = *reinterpret_cast<const float4*>(bp + 4);
                float f[8] = {fa.x, fa.y, fa.z, fa.w, fb.x, fb.y, fb.z, fb.w};
                union { __nv_bfloat16 b[8]; uint4 u; } H, L;
#pragma unroll
                for (int q = 0; q < 8; q++) {
                    H.b[q] = __float2bfloat16(f[q]);
                    L.b[q] = __float2bfloat16(f[q] - __bfloat162float(H.b[q]));
                }
                const int cpos = bk * 128 + ((bj ^ (bk & 7)) * 8);
                *reinterpret_cast<uint4*>(&Bhi[cpos]) = H.u;
                *reinterpret_cast<uint4*>(&Blo[cpos]) = L.u;
            }
            __syncthreads();

            uint32_t ahi[2][4], alo[2][4];
#pragma unroll
            for (int mt = 0; mt < 2; mt++) {
                const int rl = wm + mt * 16 + (lane & 15);
                const uint32_t aoff = (uint32_t)(rl * (A_STRIDE * 2)) + ((lane >> 4) << 4);
                ldsm_x4(ahi[mt], sAhi + aoff);
                ldsm_x4(alo[mt], sAlo + aoff);
            }
#pragma unroll
            for (int nt = 0; nt < 8; nt++) {
                const int kl = lane & 15;
                const int chunk = ((wn >> 3) + nt) ^ (kl & 7);
                const uint32_t boff = (uint32_t)(kl * 256) + (uint32_t)(chunk << 4);
                uint32_t bh0, bh1, bl0, bl1;
                ldsm_x2t(bh0, bh1, sBhi + boff);
                ldsm_x2t(bl0, bl1, sBlo + boff);
#pragma unroll
                for (int mt = 0; mt < 2; mt++) {
                    mma_bf16(acc[mt][nt], ahi[mt], bh0, bh1);
                    mma_bf16(acc[mt][nt], ahi[mt], bl0, bl1);
                    mma_bf16(acc[mt][nt], alo[mt], bh0, bh1);
                }
            }
        }
    }
    __syncthreads();

    const int g = lane >> 2;
    const int t = lane & 3;
#pragma unroll
    for (int mt = 0; mt < 2; mt++) {
        const int r0 = row0 + wm + mt * 16 + g;
        const int r1 = r0 + 8;
#pragma unroll
        for (int nt = 0; nt < 8; nt++) {
            const int c0 = wn + nt * 8 + 2 * t;
            const float bs0 = bsum[c0], bs1 = bsum[c0 + 1];
            if (r0 < M) {
                float2 v = make_float2(acc[mt][nt][0] + bs0, acc[mt][nt][1] + bs1);
                *reinterpret_cast<float2*>(C + (size_t)r0 * F + c0) = v;
                if (writeh) {
                    __half2 hv = __floats2half2_rn(v.x, v.y);
                    *reinterpret_cast<__half2*>(Ch + (size_t)r0 * F + c0) = hv;
                }
            }
            if (r1 < M) {
                float2 v = make_float2(acc[mt][nt][2] + bs0, acc[mt][nt][3] + bs1);
                *reinterpret_cast<float2*>(C + (size_t)r1 * F + c0) = v;
                if (writeh) {
                    __half2 hv = __floats2half2_rn(v.x, v.y);
                    *reinterpret_cast<__half2*>(Ch + (size_t)r1 * F + c0) = hv;
                }
            }
        }
    }
}

// ------------------------------- launcher ----------------------------------
extern "C" void kernel_launch(void* const* d_in, const int* in_sizes, int n_in,
                              void* d_out, int out_size)
{
    const float* x   = (const float*)d_in[0];
    const int*   ei1 = (const int*)  d_in[1];
    const float* ea1 = (const float*)d_in[2];
    const int*   ei2 = (const int*)  d_in[3];
    const float* ea2 = (const float*)d_in[4];

    const float* W[3][3];
    const float* Bv[3][3];
    for (int blk = 0; blk < 3; blk++)
        for (int p = 0; p < 3; p++) {
            W[blk][p]  = (const float*)d_in[5 + blk * 6 + p * 2];
            Bv[blk][p] = (const float*)d_in[5 + blk * 6 + p * 2 + 1];
        }

    const int Nn = in_sizes[0] / F;
    const int E1 = in_sizes[1] / 2;
    const int E2 = in_sizes[3] / 2;

    float *x1, *x2;
    __half *xh, *s1h, *s2h;
    int *off1, *cur1, *off2, *cur2, *part1, *part2;
    int2 *e1, *e2;
    cudaGetSymbolAddress((void**)&s1h, g_s1h);
    cudaGetSymbolAddress((void**)&s2h, g_s2h);
    cudaGetSymbolAddress((void**)&x1, g_x1);
    cudaGetSymbolAddress((void**)&x2, g_x2);
    cudaGetSymbolAddress((void**)&xh, g_xh);
    cudaGetSymbolAddress((void**)&off1, g_off1);
    cudaGetSymbolAddress((void**)&cur1, g_cur1);
    cudaGetSymbolAddress((void**)&off2, g_off2);
    cudaGetSymbolAddress((void**)&cur2, g_cur2);
    cudaGetSymbolAddress((void**)&e1, g_e1);
    cudaGetSymbolAddress((void**)&e2, g_e2);
    cudaGetSymbolAddress((void**)&part1, g_part1);
    cudaGetSymbolAddress((void**)&part2, g_part2);

    const int NB = (Nn + 511) / 512;

    // ---- CSR build + fp16 mirror of x (edges constant across blocks) ----
    cudaMemsetAsync(cur1, 0, Nn * sizeof(int), 0);
    cudaMemsetAsync(cur2, 0, Nn * sizeof(int), 0);
    f32_to_f16<<<1024, 256>>>((const float4*)x, (uint2*)xh, Nn * 32);
    hist_dual<<<2048, 256>>>(ei1 + E1, E1, cur1, ei2 + E2, E2, cur2);
    {
        dim3 gA(NB, 2);
        scanA_kernel<<<gA, 512>>>(cur1, off1, part1, cur2, off2, part2, Nn);
        scanB_kernel<<<2, 512>>>(part1, part2, NB);
        dim3 gC(256, 2);
        scanC_kernel<<<gC, 256>>>(off1, part1, cur1, off2, part2, cur2, Nn);
    }
    fill_dual<<<2048, 256>>>(ei1, ei1 + E1, ea1, E1, cur1, e1,
                             ei2, ei2 + E2, ea2, E2, cur2, e2);
    // after fill: cur[i] == off[i] + degree(i) == row end

    float* outs[3] = {x1, x2, (float*)d_out};
    const float* xin = x;
    const int sgrid = (Nn + 15) / 16;
    const int ggrid = (Nn + 127) / 128;

    for (int blk = 0; blk < 3; blk++) {
        spmm_gather<<<sgrid, 512>>>((const uint2*)xh, off1, cur1, e1,
                                    (uint2*)s1h, Nn);
        spmm_gather<<<sgrid, 512>>>((const uint2*)xh, off2, cur2, e2,
                                    (uint2*)s2h, Nn);
        gemm3_tc<<<ggrid, 256>>>(
            xin, s1h, s2h,
            W[blk][0], W[blk][1], W[blk][2],
            Bv[blk][0], Bv[blk][1], Bv[blk][2],
            outs[blk], xh, (blk < 2) ? 1 : 0, Nn);
        xin = outs[blk];
    }
}

// round 13
// speedup vs baseline: 1.5811x; 1.0187x over previous
#include <cuda_runtime.h>
#include <cuda_bf16.h>
#include <cuda_fp16.h>
#include <cstdint>

#define NMAX 100000
#define EMAX 1700000
#define F 128

// ------------------------- device-global scratch ---------------------------
__device__ __half g_s1h[(size_t)NMAX * F];   // fp16 gathered s1
__device__ __half g_s2h[(size_t)NMAX * F];   // fp16 gathered s2
__device__ float  g_x1[(size_t)NMAX * F];
__device__ float  g_x2[(size_t)NMAX * F];
__device__ __half g_xh[(size_t)NMAX * F];    // fp16 mirror of current layer input
__device__ int    g_off1[NMAX], g_cur1[NMAX];
__device__ int    g_off2[NMAX], g_cur2[NMAX];
__device__ int2   g_e1[EMAX], g_e2[EMAX];    // interleaved {src, w-bits}
__device__ int    g_part1[512], g_part2[512];

// ------------------------------- CSR build ---------------------------------
// dual-graph histogram, int4-vectorized
__global__ void hist_dual(const int* __restrict__ d1, int E1, int* __restrict__ c1,
                          const int* __restrict__ d2, int E2, int* __restrict__ c2)
{
    int i = blockIdx.x * blockDim.x + threadIdx.x;
    int stride = gridDim.x * blockDim.x;
    const int q1 = E1 >> 2, q2 = E2 >> 2;
    const int total = q1 + q2;
    for (int j = i; j < total; j += stride) {
        if (j < q1) {
            int4 v = __ldg((const int4*)d1 + j);
            atomicAdd(&c1[v.x], 1); atomicAdd(&c1[v.y], 1);
            atomicAdd(&c1[v.z], 1); atomicAdd(&c1[v.w], 1);
        } else {
            int4 v = __ldg((const int4*)d2 + (j - q1));
            atomicAdd(&c2[v.x], 1); atomicAdd(&c2[v.y], 1);
            atomicAdd(&c2[v.z], 1); atomicAdd(&c2[v.w], 1);
        }
    }
    if (i < (E1 & 3)) atomicAdd(&c1[d1[(q1 << 2) + i]], 1);
    else if (i >= 4 && i - 4 < (E2 & 3)) atomicAdd(&c2[d2[(q2 << 2) + i - 4]], 1);
}

__global__ void __launch_bounds__(512) scanA_kernel(
    const int* __restrict__ cnt1, int* __restrict__ off1, int* __restrict__ p1,
    const int* __restrict__ cnt2, int* __restrict__ off2, int* __restrict__ p2,
    int N)
{
    const int* cnt = blockIdx.y ? cnt2 : cnt1;
    int* off       = blockIdx.y ? off2 : off1;
    int* partial   = blockIdx.y ? p2   : p1;
    __shared__ int sh[512];
    int t = threadIdx.x;
    int i = blockIdx.x * 512 + t;
    int v = (i < N) ? cnt[i] : 0;
    sh[t] = v;
    __syncthreads();
#pragma unroll
    for (int d = 1; d < 512; d <<= 1) {
        int u = (t >= d) ? sh[t - d] : 0;
        __syncthreads();
        sh[t] += u;
        __syncthreads();
    }
    if (i < N) off[i] = sh[t] - v;
    if (t == 511) partial[blockIdx.x] = sh[511];
}

__global__ void __launch_bounds__(512) scanB_kernel(
    int* __restrict__ p1, int* __restrict__ p2, int NB)
{
    int* partial = blockIdx.x ? p2 : p1;
    __shared__ int sh[512];
    int t = threadIdx.x;
    int v = (t < NB) ? partial[t] : 0;
    sh[t] = v;
    __syncthreads();
#pragma unroll
    for (int d = 1; d < 512; d <<= 1) {
        int u = (t >= d) ? sh[t - d] : 0;
        __syncthreads();
        sh[t] += u;
        __syncthreads();
    }
    if (t < NB) partial[t] = sh[t] - v;
}

__global__ void scanC_kernel(int* __restrict__ off1, const int* __restrict__ p1,
                             int* __restrict__ cur1,
                             int* __restrict__ off2, const int* __restrict__ p2,
                             int* __restrict__ cur2, int N)
{
    int* off        = blockIdx.y ? off2 : off1;
    const int* pb   = blockIdx.y ? p2   : p1;
    int* cur        = blockIdx.y ? cur2 : cur1;
    int i = blockIdx.x * blockDim.x + threadIdx.x;
    int stride = gridDim.x * blockDim.x;
    for (; i < N; i += stride) {
        int o = off[i] + pb[i >> 9];
        off[i] = o;
        cur[i] = o;
    }
}

__global__ void fill_dual(
    const int* __restrict__ s1, const int* __restrict__ d1, const float* __restrict__ w1,
    int E1, int* __restrict__ c1, int2* __restrict__ eo1,
    const int* __restrict__ s2, const int* __restrict__ d2, const float* __restrict__ w2,
    int E2, int* __restrict__ c2, int2* __restrict__ eo2)
{
    int i = blockIdx.x * blockDim.x + threadIdx.x;
    int stride = gridDim.x * blockDim.x;
    const int q1 = E1 >> 2, q2 = E2 >> 2;
    const int total = q1 + q2;
    for (int j = i; j < total; j += stride) {
        if (j < q1) {
            int4   dv = __ldg((const int4*)d1 + j);
            int4   sv = __ldg((const int4*)s1 + j);
            float4 wv = __ldg((const float4*)w1 + j);
            int p;
            p = atomicAdd(&c1[dv.x], 1); eo1[p] = make_int2(sv.x, __float_as_int(wv.x));
            p = atomicAdd(&c1[dv.y], 1); eo1[p] = make_int2(sv.y, __float_as_int(wv.y));
            p = atomicAdd(&c1[dv.z], 1); eo1[p] = make_int2(sv.z, __float_as_int(wv.z));
            p = atomicAdd(&c1[dv.w], 1); eo1[p] = make_int2(sv.w, __float_as_int(wv.w));
        } else {
            int k = j - q1;
            int4   dv = __ldg((const int4*)d2 + k);
            int4   sv = __ldg((const int4*)s2 + k);
            float4 wv = __ldg((const float4*)w2 + k);
            int p;
            p = atomicAdd(&c2[dv.x], 1); eo2[p] = make_int2(sv.x, __float_as_int(wv.x));
            p = atomicAdd(&c2[dv.y], 1); eo2[p] = make_int2(sv.y, __float_as_int(wv.y));
            p = atomicAdd(&c2[dv.z], 1); eo2[p] = make_int2(sv.z, __float_as_int(wv.z));
            p = atomicAdd(&c2[dv.w], 1); eo2[p] = make_int2(sv.w, __float_as_int(wv.w));
        }
    }
    if (i < (E1 & 3)) {
        int k = (q1 << 2) + i;
        int p = atomicAdd(&c1[d1[k]], 1);
        eo1[p] = make_int2(s1[k], __float_as_int(w1[k]));
    } else if (i >= 4 && i - 4 < (E2 & 3)) {
        int k = (q2 << 2) + (i - 4);
        int p = atomicAdd(&c2[d2[k]], 1);
        eo2[p] = make_int2(s2[k], __float_as_int(w2[k]));
    }
}

// -------------------------- fp32 -> fp16 mirror ------------------------------
__global__ void f32_to_f16(const float4* __restrict__ x, uint2* __restrict__ out, int n4)
{
    int i = blockIdx.x * blockDim.x + threadIdx.x;
    int stride = gridDim.x * blockDim.x;
    for (; i < n4; i += stride) {
        float4 v = __ldg(x + i);
        __half2 h0 = __floats2half2_rn(v.x, v.y);
        __half2 h1 = __floats2half2_rn(v.z, v.w);
        out[i] = make_uint2(*(uint32_t*)&h0, *(uint32_t*)&h1);
    }
}

// -------------------------- CSR gather SpMM (fp16 in/out) --------------------
// out[row] = sum_{edges} w * xh[src]; warp per row, 4 halves per lane, MLP=8,
// smem-staged edge metadata with zero-weight padding. fp32 accumulate, fp16 out.
__global__ void __launch_bounds__(512) spmm_gather(
    const uint2* __restrict__ xh,            // [N*32], each uint2 = 4 fp16
    const int* __restrict__ off, const int* __restrict__ end,
    const int2* __restrict__ edges,
    uint2* __restrict__ outh, int N)         // fp16 out, 4 halves per lane
{
    __shared__ int2 se[16][32];

    const int wid  = threadIdx.x >> 5;
    const int lane = threadIdx.x & 31;
    const int row  = blockIdx.x * 16 + wid;
    if (row >= N) return;

    const int beg = __ldg(off + row);
    const int en  = __ldg(end + row);

    float4 acc = make_float4(0.f, 0.f, 0.f, 0.f);

    for (int j = beg; j < en; j += 32) {
        const int cnt = min(32, en - j);
        int2 e = make_int2(0, 0);                 // w = 0.0f pad -> contributes 0
        if (lane < cnt) e = __ldg(edges + j + lane);
        se[wid][lane] = e;
        __syncwarp();

        const int cnt8 = (cnt + 7) & ~7;
#pragma unroll 1
        for (int t = 0; t < cnt8; t += 8) {
            uint2 raw[8];
            float w[8];
#pragma unroll
            for (int u = 0; u < 8; u++) {
                int2 ee = se[wid][t + u];
                w[u] = __int_as_float(ee.y);
                raw[u] = __ldg(xh + (size_t)ee.x * 32 + lane);
            }
#pragma unroll
            for (int u = 0; u < 8; u++) {
                float2 a = __half22float2(*reinterpret_cast<__half2*>(&raw[u].x));
                float2 b = __half22float2(*reinterpret_cast<__half2*>(&raw[u].y));
                acc.x += w[u] * a.x;
                acc.y += w[u] * a.y;
                acc.z += w[u] * b.x;
                acc.w += w[u] * b.y;
            }
        }
        __syncwarp();
    }
    __half2 h0 = __floats2half2_rn(acc.x, acc.y);
    __half2 h1 = __floats2half2_rn(acc.z, acc.w);
    outh[(size_t)row * 32 + lane] = make_uint2(*(uint32_t*)&h0, *(uint32_t*)&h1);
}

// ---------------------- tensor-core fused 3-source GEMM ---------------------
// All A sources fp16 (xh, s1h, s2h). C fp32 out; optional fp16 mirror (written
// back into xh) for the next layer's gather. Safe aliasing: each block reads
// only its own 128 xh rows during the s=0 pass, then overwrites exactly those
// rows in the epilogue.
__device__ __forceinline__ void ldsm_x4(uint32_t* r, uint32_t addr) {
    asm volatile("ldmatrix.sync.aligned.m8n8.x4.shared.b16 {%0,%1,%2,%3}, [%4];"
                 : "=r"(r[0]), "=r"(r[1]), "=r"(r[2]), "=r"(r[3]) : "r"(addr));
}
__device__ __forceinline__ void ldsm_x2t(uint32_t& r0, uint32_t& r1, uint32_t addr) {
    asm volatile("ldmatrix.sync.aligned.m8n8.x2.trans.shared.b16 {%0,%1}, [%2];"
                 : "=r"(r0), "=r"(r1) : "r"(addr));
}
__device__ __forceinline__ void mma_bf16(float* d, const uint32_t* a, uint32_t b0, uint32_t b1) {
    asm volatile("mma.sync.aligned.m16n8k16.row.col.f32.bf16.bf16.f32 "
                 "{%0,%1,%2,%3}, {%4,%5,%6,%7}, {%8,%9}, {%0,%1,%2,%3};"
                 : "+f"(d[0]), "+f"(d[1]), "+f"(d[2]), "+f"(d[3])
                 : "r"(a[0]), "r"(a[1]), "r"(a[2]), "r"(a[3]), "r"(b0), "r"(b1));
}

#define A_STRIDE 24

__global__ void __launch_bounds__(256, 2) gemm3_tc(
    const __half* __restrict__ A0,
    const __half* __restrict__ A1, const __half* __restrict__ A2,
    const float* __restrict__ B0, const float* __restrict__ B1, const float* __restrict__ B2,
    const float* __restrict__ b0, const float* __restrict__ b1, const float* __restrict__ b2,
    float* __restrict__ C, __half* __restrict__ Ch, int writeh, int M)
{
    __shared__ __nv_bfloat16 Ahi[128 * A_STRIDE];
    __shared__ __nv_bfloat16 Alo[128 * A_STRIDE];
    __shared__ __nv_bfloat16 Bhi[16 * 128];
    __shared__ __nv_bfloat16 Blo[16 * 128];
    __shared__ float bsum[128];

    const int tid  = threadIdx.x;
    const int lane = tid & 31;
    const int wid  = tid >> 5;
    const int row0 = blockIdx.x * 128;

    const int wm = (wid >> 1) * 32;
    const int wn = (wid & 1) * 64;

    if (tid < 128) bsum[tid] = __ldg(b0 + tid) + __ldg(b1 + tid) + __ldg(b2 + tid);

    float acc[2][8][4];
#pragma unroll
    for (int mt = 0; mt < 2; mt++)
#pragma unroll
        for (int nt = 0; nt < 8; nt++)
#pragma unroll
            for (int q = 0; q < 4; q++) acc[mt][nt][q] = 0.f;

    const int alr   = tid >> 1;
    const int akoff = (tid & 1) * 8;
    const bool arow_ok = (row0 + alr) < M;
    const int bk = tid >> 4;
    const int bj = tid & 15;

    const uint32_t sAhi = (uint32_t)__cvta_generic_to_shared(Ahi);
    const uint32_t sAlo = (uint32_t)__cvta_generic_to_shared(Alo);
    const uint32_t sBhi = (uint32_t)__cvta_generic_to_shared(Bhi);
    const uint32_t sBlo = (uint32_t)__cvta_generic_to_shared(Blo);

    const __half* Alist[3] = {A0, A1, A2};
    const float*  Blist[3] = {B0, B1, B2};

    for (int s = 0; s < 3; s++) {
        const __half* A = Alist[s];
        const float*  B = Blist[s];

#pragma unroll 1
        for (int kk = 0; kk < 8; kk++) {
            const int k0 = kk * 16;
            __syncthreads();

            {
                float f[8] = {0, 0, 0, 0, 0, 0, 0, 0};
                if (arow_ok) {
                    const __half* ap = A + (size_t)(row0 + alr) * F + k0 + akoff;
                    uint4 hv = *reinterpret_cast<const uint4*>(ap);
                    float2 p0 = __half22float2(*reinterpret_cast<__half2*>(&hv.x));
                    float2 p1 = __half22float2(*reinterpret_cast<__half2*>(&hv.y));
                    float2 p2 = __half22float2(*reinterpret_cast<__half2*>(&hv.z));
                    float2 p3 = __half22float2(*reinterpret_cast<__half2*>(&hv.w));
                    f[0] = p0.x; f[1] = p0.y; f[2] = p1.x; f[3] = p1.y;
                    f[4] = p2.x; f[5] = p2.y; f[6] = p3.x; f[7] = p3.y;
                }
                union { __nv_bfloat16 b[8]; uint4 u; } H, L;
#pragma unroll
                for (int q = 0; q < 8; q++) {
                    H.b[q] = __float2bfloat16(f[q]);
                    L.b[q] = __float2bfloat16(f[q] - __bfloat162float(H.b[q]));
                }
                *reinterpret_cast<uint4*>(&Ahi[alr * A_STRIDE + akoff]) = H.u;
                *reinterpret_cast<uint4*>(&Alo[alr * A_STRIDE + akoff]) = L.u;
            }
            {
                const float* bp = B + (size_t)(k0 + bk) * F + bj * 8;
                float4 fa = *reinterpret_cast<const float4*>(bp);
                float4 fb = *reinterpret_cast<const float4*>(bp + 4);
                float f[8] = {fa.x, fa.y, fa.z, fa.w, fb.x, fb.y, fb.z, fb.w};
                union { __nv_bfloat16 b[8]; uint4 u; } H, L;
#pragma unroll
                for (int q = 0; q < 8; q++) {
                    H.b[q] = __float2bfloat16(f[q]);
                    L.b[q] = __float2bfloat16(f[q] - __bfloat162float(H.b[q]));
                }
                const int cpos = bk * 128 + ((bj ^ (bk & 7)) * 8);
                *reinterpret_cast<uint4*>(&Bhi[cpos]) = H.u;
                *reinterpret_cast<uint4*>(&Blo[cpos]) = L.u;
            }
            __syncthreads();

            uint32_t ahi[2][4], alo[2][4];
#pragma unroll
            for (int mt = 0; mt < 2; mt++) {
                const int rl = wm + mt * 16 + (lane & 15);
                const uint32_t aoff = (uint32_t)(rl * (A_STRIDE * 2)) + ((lane >> 4) << 4);
                ldsm_x4(ahi[mt], sAhi + aoff);
                ldsm_x4(alo[mt], sAlo + aoff);
            }
#pragma unroll
            for (int nt = 0; nt < 8; nt++) {
                const int kl = lane & 15;
                const int chunk = ((wn >> 3) + nt) ^ (kl & 7);
                const uint32_t boff = (uint32_t)(kl * 256) + (uint32_t)(chunk << 4);
                uint32_t bh0, bh1, bl0, bl1;
                ldsm_x2t(bh0, bh1, sBhi + boff);
                ldsm_x2t(bl0, bl1, sBlo + boff);
#pragma unroll
                for (int mt = 0; mt < 2; mt++) {
                    mma_bf16(acc[mt][nt], ahi[mt], bh0, bh1);
                    mma_bf16(acc[mt][nt], ahi[mt], bl0, bl1);
                    mma_bf16(acc[mt][nt], alo[mt], bh0, bh1);
                }
            }
        }
    }
    __syncthreads();

    const int g = lane >> 2;
    const int t = lane & 3;
#pragma unroll
    for (int mt = 0; mt < 2; mt++) {
        const int r0 = row0 + wm + mt * 16 + g;
        const int r1 = r0 + 8;
#pragma unroll
        for (int nt = 0; nt < 8; nt++) {
            const int c0 = wn + nt * 8 + 2 * t;
            const float bs0 = bsum[c0], bs1 = bsum[c0 + 1];
            if (r0 < M) {
                float2 v = make_float2(acc[mt][nt][0] + bs0, acc[mt][nt][1] + bs1);
                *reinterpret_cast<float2*>(C + (size_t)r0 * F + c0) = v;
                if (writeh) {
                    __half2 hv = __floats2half2_rn(v.x, v.y);
                    *reinterpret_cast<__half2*>(Ch + (size_t)r0 * F + c0) = hv;
                }
            }
            if (r1 < M) {
                float2 v = make_float2(acc[mt][nt][2] + bs0, acc[mt][nt][3] + bs1);
                *reinterpret_cast<float2*>(C + (size_t)r1 * F + c0) = v;
                if (writeh) {
                    __half2 hv = __floats2half2_rn(v.x, v.y);
                    *reinterpret_cast<__half2*>(Ch + (size_t)r1 * F + c0) = hv;
                }
            }
        }
    }
}

// ------------------------------- launcher ----------------------------------
extern "C" void kernel_launch(void* const* d_in, const int* in_sizes, int n_in,
                              void* d_out, int out_size)
{
    const float* x   = (const float*)d_in[0];
    const int*   ei1 = (const int*)  d_in[1];
    const float* ea1 = (const float*)d_in[2];
    const int*   ei2 = (const int*)  d_in[3];
    const float* ea2 = (const float*)d_in[4];

    const float* W[3][3];
    const float* Bv[3][3];
    for (int blk = 0; blk < 3; blk++)
        for (int p = 0; p < 3; p++) {
            W[blk][p]  = (const float*)d_in[5 + blk * 6 + p * 2];
            Bv[blk][p] = (const float*)d_in[5 + blk * 6 + p * 2 + 1];
        }

    const int Nn = in_sizes[0] / F;
    const int E1 = in_sizes[1] / 2;
    const int E2 = in_sizes[3] / 2;

    float *x1, *x2;
    __half *xh, *s1h, *s2h;
    int *off1, *cur1, *off2, *cur2, *part1, *part2;
    int2 *e1, *e2;
    cudaGetSymbolAddress((void**)&s1h, g_s1h);
    cudaGetSymbolAddress((void**)&s2h, g_s2h);
    cudaGetSymbolAddress((void**)&x1, g_x1);
    cudaGetSymbolAddress((void**)&x2, g_x2);
    cudaGetSymbolAddress((void**)&xh, g_xh);
    cudaGetSymbolAddress((void**)&off1, g_off1);
    cudaGetSymbolAddress((void**)&cur1, g_cur1);
    cudaGetSymbolAddress((void**)&off2, g_off2);
    cudaGetSymbolAddress((void**)&cur2, g_cur2);
    cudaGetSymbolAddress((void**)&e1, g_e1);
    cudaGetSymbolAddress((void**)&e2, g_e2);
    cudaGetSymbolAddress((void**)&part1, g_part1);
    cudaGetSymbolAddress((void**)&part2, g_part2);

    const int NB = (Nn + 511) / 512;

    // ---- CSR build + fp16 mirror of x (edges constant across blocks) ----
    cudaMemsetAsync(cur1, 0, Nn * sizeof(int), 0);
    cudaMemsetAsync(cur2, 0, Nn * sizeof(int), 0);
    f32_to_f16<<<1024, 256>>>((const float4*)x, (uint2*)xh, Nn * 32);
    hist_dual<<<1024, 256>>>(ei1 + E1, E1, cur1, ei2 + E2, E2, cur2);
    {
        dim3 gA(NB, 2);
        scanA_kernel<<<gA, 512>>>(cur1, off1, part1, cur2, off2, part2, Nn);
        scanB_kernel<<<2, 512>>>(part1, part2, NB);
        dim3 gC(256, 2);
        scanC_kernel<<<gC, 256>>>(off1, part1, cur1, off2, part2, cur2, Nn);
    }
    fill_dual<<<1024, 256>>>(ei1, ei1 + E1, ea1, E1, cur1, e1,
                             ei2, ei2 + E2, ea2, E2, cur2, e2);
    // after fill: cur[i] == off[i] + degree(i) == row end

    float* outs[3] = {x1, x2, (float*)d_out};
    const int sgrid = (Nn + 15) / 16;
    const int ggrid = (Nn + 127) / 128;

    for (int blk = 0; blk < 3; blk++) {
        spmm_gather<<<sgrid, 512>>>((const uint2*)xh, off1, cur1, e1,
                                    (uint2*)s1h, Nn);
        spmm_gather<<<sgrid, 512>>>((const uint2*)xh, off2, cur2, e2,
                                    (uint2*)s2h, Nn);
        gemm3_tc<<<ggrid, 256>>>(
            xh, s1h, s2h,
            W[blk][0], W[blk][1], W[blk][2],
            Bv[blk][0], Bv[blk][1], Bv[blk][2],
            outs[blk], xh, (blk < 2) ? 1 : 0, Nn);
    }
}